// round 4
// baseline (speedup 1.0000x reference)
#include <cuda_runtime.h>
#include <cfloat>

// Problem constants
#define B_    8
#define S_    4096
#define D_    1024
#define DS_   64
#define MTOT  32768      // B_*S_
#define NU    960        // used neurons: 512 + 256 + 128 + 64 (N_KNOW unused)

// Scratch (device globals — allocation-free per harness rules)
__device__ float g_embn[NU * DS_];                 // normalized embeddings [960][64]
__device__ float g_h[(size_t)MTOT * DS_];          // h = x@W^T + b        [32768][64]
__device__ float g_L[(size_t)MTOT * NU];           // logits               [32768][960]
__device__ float g_coef[MTOT * 4];                 // imp/Z per group      [32768][4]
__device__ float g_wpart[B_ * 32 * NU];            // per-chunk partial w  [8][32][960]

// ---------------- f32x2 packed-FMA helpers (FFMA2) ----------------
__device__ __forceinline__ unsigned long long pk2(float lo, float hi) {
    unsigned long long r;
    asm("mov.b64 %0, {%1, %2};" : "=l"(r) : "f"(lo), "f"(hi));
    return r;
}
__device__ __forceinline__ void fma2(unsigned long long& acc,
                                     unsigned long long a, unsigned long long b) {
    asm("fma.rn.f32x2 %0, %1, %2, %0;" : "+l"(acc) : "l"(a), "l"(b));
}
__device__ __forceinline__ float2 upk2(unsigned long long v) {
    float2 f;
    asm("mov.b64 {%0, %1}, %2;" : "=f"(f.x), "=f"(f.y) : "l"(v));
    return f;
}

// ---------------- K0: normalize neuron embeddings (first 960 rows) ----------------
__global__ void k_norm(const float* __restrict__ emb) {
    int lane = threadIdx.x;
    int n = blockIdx.x * 8 + threadIdx.y;
    if (n >= NU) return;
    float v0 = emb[n * 64 + lane];
    float v1 = emb[n * 64 + 32 + lane];
    float ss = v0 * v0 + v1 * v1;
#pragma unroll
    for (int off = 16; off; off >>= 1) ss += __shfl_xor_sync(0xffffffffu, ss, off);
    float inv = rsqrtf(ss);
    g_embn[n * 64 + lane]      = v0 * inv;
    g_embn[n * 64 + 32 + lane] = v1 * inv;
}

// ---------------- K1: h[M][64] = x[M][1024] @ W[64][1024]^T + bias ----------------
// BM=128, BN=64 (full), BK=32; 128 threads; per-thread 8x8 tile with f32x2 n-pairs.
__global__ __launch_bounds__(128) void k_gemm1(const float* __restrict__ x,
                                               const float* __restrict__ W,
                                               const float* __restrict__ bias) {
    __shared__ float sA[32][132];   // [k][m], padded
    __shared__ float sB[32][68];    // [k][n], padded (pad keeps 16B align)
    int tid = threadIdx.x;
    int txn = tid & 7;              // n-group (8 groups x 8 = 64)
    int tym = tid >> 3;             // m-group (16 groups x 8 = 128)
    int m0  = blockIdx.x * 128;

    unsigned long long acc[8][4];
#pragma unroll
    for (int i = 0; i < 8; i++)
#pragma unroll
        for (int j = 0; j < 4; j++) acc[i][j] = 0ull;

    for (int kb = 0; kb < D_; kb += 32) {
        // load A tile (128x32), transposed into smem
#pragma unroll
        for (int it = 0; it < 8; ++it) {
            int i = it * 128 + tid; int m = i >> 3; int c = i & 7;
            float4 v = *(const float4*)(x + (size_t)(m0 + m) * D_ + kb + c * 4);
            sA[c * 4 + 0][m] = v.x; sA[c * 4 + 1][m] = v.y;
            sA[c * 4 + 2][m] = v.z; sA[c * 4 + 3][m] = v.w;
        }
        // load B tile (W: 64x32), transposed
#pragma unroll
        for (int it = 0; it < 4; ++it) {
            int i = it * 128 + tid; int n = i >> 3; int c = i & 7;
            float4 v = *(const float4*)(W + (size_t)n * D_ + kb + c * 4);
            sB[c * 4 + 0][n] = v.x; sB[c * 4 + 1][n] = v.y;
            sB[c * 4 + 2][n] = v.z; sB[c * 4 + 3][n] = v.w;
        }
        __syncthreads();
#pragma unroll 8
        for (int kk = 0; kk < 32; ++kk) {
            float4 a0 = *(const float4*)&sA[kk][tym * 8];
            float4 a1 = *(const float4*)&sA[kk][tym * 8 + 4];
            float4 b0 = *(const float4*)&sB[kk][txn * 8];
            float4 b1 = *(const float4*)&sB[kk][txn * 8 + 4];
            unsigned long long bb[4] = { pk2(b0.x, b0.y), pk2(b0.z, b0.w),
                                         pk2(b1.x, b1.y), pk2(b1.z, b1.w) };
            float av[8] = { a0.x, a0.y, a0.z, a0.w, a1.x, a1.y, a1.z, a1.w };
#pragma unroll
            for (int i = 0; i < 8; i++) {
                unsigned long long ad = pk2(av[i], av[i]);
#pragma unroll
                for (int j = 0; j < 4; j++) fma2(acc[i][j], ad, bb[j]);
            }
        }
        __syncthreads();
    }
    // epilogue: + bias, store h
#pragma unroll
    for (int i = 0; i < 8; i++) {
        int row = m0 + tym * 8 + i;
        float o[8];
#pragma unroll
        for (int j = 0; j < 4; j++) { float2 f = upk2(acc[i][j]); o[2 * j] = f.x; o[2 * j + 1] = f.y; }
#pragma unroll
        for (int j = 0; j < 8; j++) o[j] += bias[txn * 8 + j];
        *(float4*)(g_h + (size_t)row * DS_ + txn * 8)     = make_float4(o[0], o[1], o[2], o[3]);
        *(float4*)(g_h + (size_t)row * DS_ + txn * 8 + 4) = make_float4(o[4], o[5], o[6], o[7]);
    }
}

// ---------------- K2: L[M][960] = h[M][64] @ embn[960][64]^T ----------------
// BM=128, BN=128 (padded to 1024 n total, guard stores), BK=32; 256 threads; 8x8 tiles.
__global__ __launch_bounds__(256) void k_gemm2() {
    __shared__ float sA[32][132];   // [k][m]
    __shared__ float sB[32][132];   // [k][n]
    int tid = threadIdx.x;
    int txn = tid & 15;             // 16 n-groups x 8 = 128
    int tym = tid >> 4;             // 16 m-groups x 8 = 128
    int m0  = blockIdx.x * 128;
    int n0b = blockIdx.y * 128;

    unsigned long long acc[8][4];
#pragma unroll
    for (int i = 0; i < 8; i++)
#pragma unroll
        for (int j = 0; j < 4; j++) acc[i][j] = 0ull;

    for (int kb = 0; kb < DS_; kb += 32) {
#pragma unroll
        for (int it = 0; it < 4; ++it) {
            int i = it * 256 + tid; int m = i >> 3; int c = i & 7;
            float4 v = *(const float4*)(g_h + (size_t)(m0 + m) * DS_ + kb + c * 4);
            sA[c * 4 + 0][m] = v.x; sA[c * 4 + 1][m] = v.y;
            sA[c * 4 + 2][m] = v.z; sA[c * 4 + 3][m] = v.w;
        }
#pragma unroll
        for (int it = 0; it < 4; ++it) {
            int i = it * 256 + tid; int n = i >> 3; int c = i & 7;
            int gn = n0b + n;
            float4 v = (gn < NU)
                ? *(const float4*)(g_embn + (size_t)gn * DS_ + kb + c * 4)
                : make_float4(0.f, 0.f, 0.f, 0.f);
            sB[c * 4 + 0][n] = v.x; sB[c * 4 + 1][n] = v.y;
            sB[c * 4 + 2][n] = v.z; sB[c * 4 + 3][n] = v.w;
        }
        __syncthreads();
#pragma unroll 8
        for (int kk = 0; kk < 32; ++kk) {
            float4 a0 = *(const float4*)&sA[kk][tym * 8];
            float4 a1 = *(const float4*)&sA[kk][tym * 8 + 4];
            float4 b0 = *(const float4*)&sB[kk][txn * 8];
            float4 b1 = *(const float4*)&sB[kk][txn * 8 + 4];
            unsigned long long bb[4] = { pk2(b0.x, b0.y), pk2(b0.z, b0.w),
                                         pk2(b1.x, b1.y), pk2(b1.z, b1.w) };
            float av[8] = { a0.x, a0.y, a0.z, a0.w, a1.x, a1.y, a1.z, a1.w };
#pragma unroll
            for (int i = 0; i < 8; i++) {
                unsigned long long ad = pk2(av[i], av[i]);
#pragma unroll
                for (int j = 0; j < 4; j++) fma2(acc[i][j], ad, bb[j]);
            }
        }
        __syncthreads();
    }
#pragma unroll
    for (int i = 0; i < 8; i++) {
        int row = m0 + tym * 8 + i;
        int nc  = n0b + txn * 8;
        if (nc < NU) {
            float o[8];
#pragma unroll
            for (int j = 0; j < 4; j++) { float2 f = upk2(acc[i][j]); o[2 * j] = f.x; o[2 * j + 1] = f.y; }
            *(float4*)(g_L + (size_t)row * NU + nc)     = make_float4(o[0], o[1], o[2], o[3]);
            *(float4*)(g_L + (size_t)row * NU + nc + 4) = make_float4(o[4], o[5], o[6], o[7]);
        }
    }
}

// ---------------- K3: per-row group softmax normalizers -> coef = imp / Z ----------------
// One warp per row; no max-subtraction (logits ~ N(0,1), no overflow risk).
__global__ void k_soft(const float* __restrict__ imp) {
    int lane = threadIdx.x & 31;
    int w    = threadIdx.x >> 5;
    int s    = blockIdx.x * 8 + w;
    const float* Ls = g_L + (size_t)s * NU;
    float s0 = 0.f, s1 = 0.f, s2 = 0.f, s3 = 0.f;
    for (int j = lane; j < NU; j += 32) {
        float e = __expf(Ls[j]);
        if      (j < 512) s0 += e;
        else if (j < 768) s1 += e;
        else if (j < 896) s2 += e;
        else              s3 += e;
    }
#pragma unroll
    for (int off = 16; off; off >>= 1) {
        s0 += __shfl_xor_sync(0xffffffffu, s0, off);
        s1 += __shfl_xor_sync(0xffffffffu, s1, off);
        s2 += __shfl_xor_sync(0xffffffffu, s2, off);
        s3 += __shfl_xor_sync(0xffffffffu, s3, off);
    }
    if (lane == 0) {
        float im = imp[s];
        *(float4*)(g_coef + s * 4) = make_float4(im / s0, im / s1, im / s2, im / s3);
    }
}

// ---------------- K4: deterministic per-chunk accumulation ----------------
// grid (32 chunks, 8 batches); each block reduces 128 rows into w_part[b][chunk][960].
__global__ void k_accum() {
    int b = blockIdx.y, c = blockIdx.x, t = threadIdx.x;
    float a0 = 0.f, a1 = 0.f, a2 = 0.f, a3 = 0.f;
    int base_s = b * S_ + c * 128;
    for (int r = 0; r < 128; r++) {
        int s = base_s + r;
        float4 cf = *(const float4*)(g_coef + s * 4);
        const float* Ls = g_L + (size_t)s * NU;
        a0 += cf.x * __expf(Ls[t]);          // n = t        in [0,256)   -> group 0
        a1 += cf.x * __expf(Ls[t + 256]);    // n in [256,512)            -> group 0
        a2 += cf.y * __expf(Ls[t + 512]);    // n in [512,768)            -> group 1
        if (t < 192) {
            float cg = (t < 128) ? cf.z : cf.w;  // [768,896)->g2, [896,960)->g3
            a3 += cg * __expf(Ls[t + 768]);
        }
    }
    float* wp = g_wpart + (size_t)(b * 32 + c) * NU;
    wp[t] = a0; wp[t + 256] = a1; wp[t + 512] = a2;
    if (t < 192) wp[t + 768] = a3;
}

// ---------------- K5: reduce partials + top-k + output formatting ----------------
// jax top_k tie-break: lowest index wins on equal values.
__device__ void warp_topk_mark(float* v, int size, int k) {
    unsigned lane = threadIdx.x & 31;
    for (int p = 0; p < k; p++) {
        float bv = -FLT_MAX; int bi = 0x7fffffff;
        for (int j = (int)lane; j < size; j += 32) {
            float val = v[j];
            if (val > bv) { bv = val; bi = j; }
        }
#pragma unroll
        for (int off = 16; off; off >>= 1) {
            float ov = __shfl_down_sync(0xffffffffu, bv, off);
            int   oi = __shfl_down_sync(0xffffffffu, bi, off);
            if (ov > bv || (ov == bv && oi < bi)) { bv = ov; bi = oi; }
        }
        bi = __shfl_sync(0xffffffffu, bi, 0);
        if (lane == 0) v[bi] = -FLT_MAX;   // sentinel mark (all real w > 0)
        __syncwarp();
    }
}

__global__ void k_final(float* __restrict__ out) {
    __shared__ float sw[NU];
    __shared__ float relv[128];
    __shared__ float valv[64];
    int b = blockIdx.x, t = threadIdx.x;
    for (int n = t; n < NU; n += 256) {
        float a = 0.f;
#pragma unroll
        for (int c = 0; c < 32; c++) a += g_wpart[(size_t)(b * 32 + c) * NU + n];
        sw[n] = a;
    }
    __syncthreads();
    if (t < 32) {
        for (int j = t; j < 128; j += 32) relv[j] = sw[768 + j];
        for (int j = t; j < 64;  j += 32) valv[j] = sw[896 + j];
        __syncwarp();
        warp_topk_mark(sw,        512, 64);   // qk indices
        warp_topk_mark(sw + 512,  256, 32);   // v  indices
        warp_topk_mark(sw + 768,  128, 16);   // rel sparse
        warp_topk_mark(sw + 896,   64,  3);   // val sparse
        if (t == 0) {
            int c = 0;
            for (int n = 0; n < 512; n++)
                if (sw[n] == -FLT_MAX) out[b * 64 + (c++)] = (float)n;        // idx_qk sorted
            c = 0;
            for (int n = 0; n < 256; n++)
                if (sw[512 + n] == -FLT_MAX) out[512 + b * 32 + (c++)] = (float)n;  // idx_v sorted
        }
        for (int n = t; n < 128; n += 32) {
            float val = (sw[768 + n] == -FLT_MAX) ? relv[n] : 0.f;
            out[768  + b * 128 + n] = val;   // rel_Q
            out[1792 + b * 128 + n] = val;   // rel_K (identical by construction)
        }
        for (int n = t; n < 64; n += 32) {
            float val = (sw[896 + n] == -FLT_MAX) ? valv[n] : 0.f;
            out[2816 + b * 64 + n] = val;    // val_w
        }
    }
}

// ---------------- launch ----------------
extern "C" void kernel_launch(void* const* d_in, const int* in_sizes, int n_in,
                              void* d_out, int out_size) {
    const float* x    = (const float*)d_in[0];
    const float* imp  = (const float*)d_in[1];
    const float* W    = (const float*)d_in[2];
    const float* bias = (const float*)d_in[3];
    const float* emb  = (const float*)d_in[4];
    float* out = (float*)d_out;

    k_norm<<<120, dim3(32, 8)>>>(emb);
    k_gemm1<<<MTOT / 128, 128>>>(x, W, bias);
    k_gemm2<<<dim3(MTOT / 128, 8), 256>>>();
    k_soft<<<MTOT / 8, 256>>>(imp);
    k_accum<<<dim3(32, B_), 256>>>();
    k_final<<<B_, 256>>>(out);
}

// round 5
// speedup vs baseline: 1.1072x; 1.1072x over previous
#include <cuda_runtime.h>
#include <cfloat>

// Problem constants
#define B_    8
#define S_    4096
#define D_    1024
#define DS_   64
#define MTOT  32768      // B_*S_
#define NU    960        // used neurons: 512 + 256 + 128 + 64 (N_KNOW unused)

// Scratch (device globals — allocation-free per harness rules)
__device__ float g_embn[NU * DS_];                 // normalized embeddings [960][64]
__device__ float g_h[(size_t)MTOT * DS_];          // h = x@W^T + b        [32768][64]
__device__ float g_E[(size_t)MTOT * NU];           // exp(logits)          [32768][960]
__device__ float g_Zpart[8 * MTOT];                // per-slab exp sums    [by][32768]
__device__ float g_coef[MTOT * 4];                 // imp/Z per group      [32768][4]
__device__ float g_wpart[B_ * 32 * NU];            // per-chunk partial w  [8][32][960]

// ---------------- f32x2 packed-FMA helpers (FFMA2) ----------------
__device__ __forceinline__ unsigned long long pk2(float lo, float hi) {
    unsigned long long r;
    asm("mov.b64 %0, {%1, %2};" : "=l"(r) : "f"(lo), "f"(hi));
    return r;
}
__device__ __forceinline__ void fma2(unsigned long long& acc,
                                     unsigned long long a, unsigned long long b) {
    asm("fma.rn.f32x2 %0, %1, %2, %0;" : "+l"(acc) : "l"(a), "l"(b));
}
__device__ __forceinline__ float2 upk2(unsigned long long v) {
    float2 f;
    asm("mov.b64 {%0, %1}, %2;" : "=f"(f.x), "=f"(f.y) : "l"(v));
    return f;
}

// ---------------- K0: normalize neuron embeddings (first 960 rows) ----------------
__global__ void k_norm(const float* __restrict__ emb) {
    int lane = threadIdx.x;
    int n = blockIdx.x * 8 + threadIdx.y;
    if (n >= NU) return;
    float v0 = emb[n * 64 + lane];
    float v1 = emb[n * 64 + 32 + lane];
    float ss = v0 * v0 + v1 * v1;
#pragma unroll
    for (int off = 16; off; off >>= 1) ss += __shfl_xor_sync(0xffffffffu, ss, off);
    float inv = rsqrtf(ss);
    g_embn[n * 64 + lane]      = v0 * inv;
    g_embn[n * 64 + 32 + lane] = v1 * inv;
}

// ---------------- K1: h[M][64] = x[M][1024] @ W[64][1024]^T + bias ----------------
// BM=128, BN=64 (full), BK=32; 128 threads; per-thread 8x8 tile with f32x2 n-pairs.
__global__ __launch_bounds__(128) void k_gemm1(const float* __restrict__ x,
                                               const float* __restrict__ W,
                                               const float* __restrict__ bias) {
    __shared__ __align__(16) float sA[32][132];   // [k][m], padded (row=528B, 16B-mult)
    __shared__ __align__(16) float sB[32][68];    // [k][n], padded (row=272B, 16B-mult)
    int tid = threadIdx.x;
    int txn = tid & 7;              // n-group (8 groups x 8 = 64)
    int tym = tid >> 3;             // m-group (16 groups x 8 = 128)
    int m0  = blockIdx.x * 128;

    unsigned long long acc[8][4];
#pragma unroll
    for (int i = 0; i < 8; i++)
#pragma unroll
        for (int j = 0; j < 4; j++) acc[i][j] = 0ull;

    for (int kb = 0; kb < D_; kb += 32) {
        // load A tile (128x32), transposed into smem
#pragma unroll
        for (int it = 0; it < 8; ++it) {
            int i = it * 128 + tid; int m = i >> 3; int c = i & 7;
            float4 v = *(const float4*)(x + (size_t)(m0 + m) * D_ + kb + c * 4);
            sA[c * 4 + 0][m] = v.x; sA[c * 4 + 1][m] = v.y;
            sA[c * 4 + 2][m] = v.z; sA[c * 4 + 3][m] = v.w;
        }
        // load B tile (W: 64x32), transposed
#pragma unroll
        for (int it = 0; it < 4; ++it) {
            int i = it * 128 + tid; int n = i >> 3; int c = i & 7;
            float4 v = *(const float4*)(W + (size_t)n * D_ + kb + c * 4);
            sB[c * 4 + 0][n] = v.x; sB[c * 4 + 1][n] = v.y;
            sB[c * 4 + 2][n] = v.z; sB[c * 4 + 3][n] = v.w;
        }
        __syncthreads();
#pragma unroll 8
        for (int kk = 0; kk < 32; ++kk) {
            float4 a0 = *(const float4*)&sA[kk][tym * 8];
            float4 a1 = *(const float4*)&sA[kk][tym * 8 + 4];
            // B n-pairs are already f32x2 bit patterns in smem — read directly.
            ulonglong2 b01 = *(const ulonglong2*)&sB[kk][txn * 8];
            ulonglong2 b23 = *(const ulonglong2*)&sB[kk][txn * 8 + 4];
            unsigned long long bb[4] = { b01.x, b01.y, b23.x, b23.y };
            float av[8] = { a0.x, a0.y, a0.z, a0.w, a1.x, a1.y, a1.z, a1.w };
#pragma unroll
            for (int i = 0; i < 8; i++) {
                unsigned long long ad = pk2(av[i], av[i]);
#pragma unroll
                for (int j = 0; j < 4; j++) fma2(acc[i][j], ad, bb[j]);
            }
        }
        __syncthreads();
    }
    // epilogue: + bias, store h
#pragma unroll
    for (int i = 0; i < 8; i++) {
        int row = m0 + tym * 8 + i;
        float o[8];
#pragma unroll
        for (int j = 0; j < 4; j++) { float2 f = upk2(acc[i][j]); o[2 * j] = f.x; o[2 * j + 1] = f.y; }
#pragma unroll
        for (int j = 0; j < 8; j++) o[j] += bias[txn * 8 + j];
        *(float4*)(g_h + (size_t)row * DS_ + txn * 8)     = make_float4(o[0], o[1], o[2], o[3]);
        *(float4*)(g_h + (size_t)row * DS_ + txn * 8 + 4) = make_float4(o[4], o[5], o[6], o[7]);
    }
}

// ---------------- K2: E[M][960] = exp(h @ embn^T), plus per-slab softmax partials ----
// BM=128, BN=128 (padded to 1024 n, guard stores), BK=32; 256 threads; 8x8 tiles.
// Each blockIdx.y slab of 128 columns lies entirely inside one softmax group
// (boundaries 512/768/896 are multiples of 128), so the block reduces its own
// exp-sums per row and writes a deterministic partial Zpart[by][s].
__global__ __launch_bounds__(256) void k_gemm2() {
    __shared__ __align__(16) float sA[32][132];   // [k][m]
    __shared__ __align__(16) float sB[32][132];   // [k][n]
    int tid = threadIdx.x;
    int txn = tid & 15;             // 16 n-groups x 8 = 128
    int tym = tid >> 4;             // 16 m-groups x 8 = 128
    int m0  = blockIdx.x * 128;
    int n0b = blockIdx.y * 128;

    unsigned long long acc[8][4];
#pragma unroll
    for (int i = 0; i < 8; i++)
#pragma unroll
        for (int j = 0; j < 4; j++) acc[i][j] = 0ull;

    for (int kb = 0; kb < DS_; kb += 32) {
#pragma unroll
        for (int it = 0; it < 4; ++it) {
            int i = it * 256 + tid; int m = i >> 3; int c = i & 7;
            float4 v = *(const float4*)(g_h + (size_t)(m0 + m) * DS_ + kb + c * 4);
            sA[c * 4 + 0][m] = v.x; sA[c * 4 + 1][m] = v.y;
            sA[c * 4 + 2][m] = v.z; sA[c * 4 + 3][m] = v.w;
        }
#pragma unroll
        for (int it = 0; it < 4; ++it) {
            int i = it * 256 + tid; int n = i >> 3; int c = i & 7;
            int gn = n0b + n;
            float4 v = (gn < NU)
                ? *(const float4*)(g_embn + (size_t)gn * DS_ + kb + c * 4)
                : make_float4(0.f, 0.f, 0.f, 0.f);
            sB[c * 4 + 0][n] = v.x; sB[c * 4 + 1][n] = v.y;
            sB[c * 4 + 2][n] = v.z; sB[c * 4 + 3][n] = v.w;
        }
        __syncthreads();
#pragma unroll 8
        for (int kk = 0; kk < 32; ++kk) {
            float4 a0 = *(const float4*)&sA[kk][tym * 8];
            float4 a1 = *(const float4*)&sA[kk][tym * 8 + 4];
            ulonglong2 b01 = *(const ulonglong2*)&sB[kk][txn * 8];
            ulonglong2 b23 = *(const ulonglong2*)&sB[kk][txn * 8 + 4];
            unsigned long long bb[4] = { b01.x, b01.y, b23.x, b23.y };
            float av[8] = { a0.x, a0.y, a0.z, a0.w, a1.x, a1.y, a1.z, a1.w };
#pragma unroll
            for (int i = 0; i < 8; i++) {
                unsigned long long ad = pk2(av[i], av[i]);
#pragma unroll
                for (int j = 0; j < 4; j++) fma2(acc[i][j], ad, bb[j]);
            }
        }
        __syncthreads();
    }

    // ---- epilogue: exp, store E, per-row slab sums -> Zpart ----
    int nc = n0b + txn * 8;
    bool valid = (nc < NU);         // per-thread: either all 8 cols valid or none
    float rsum[8];
#pragma unroll
    for (int i = 0; i < 8; i++) {
        float rs = 0.f;
        if (valid) {
            int row = m0 + tym * 8 + i;
            float o[8];
#pragma unroll
            for (int j = 0; j < 4; j++) { float2 f = upk2(acc[i][j]); o[2 * j] = f.x; o[2 * j + 1] = f.y; }
#pragma unroll
            for (int j = 0; j < 8; j++) { o[j] = __expf(o[j]); rs += o[j]; }
            *(float4*)(g_E + (size_t)row * NU + nc)     = make_float4(o[0], o[1], o[2], o[3]);
            *(float4*)(g_E + (size_t)row * NU + nc + 4) = make_float4(o[4], o[5], o[6], o[7]);
        }
        rsum[i] = rs;
    }
    // reduce the 16 txn partials per row (reuse sA storage; safe after final barrier)
    float* sred = &sA[0][0];        // needs 128*17 floats, sA has 4224
#pragma unroll
    for (int i = 0; i < 8; i++) sred[(tym * 8 + i) * 17 + txn] = rsum[i];
    __syncthreads();
    if (tid < 128) {
        float z = 0.f;
#pragma unroll
        for (int i = 0; i < 16; i++) z += sred[tid * 17 + i];
        g_Zpart[blockIdx.y * MTOT + m0 + tid] = z;
    }
}

// ---------------- K3: fold slab partials + importance -> coef = imp/Z ----------------
__global__ void k_coef(const float* __restrict__ imp) {
    int s = blockIdx.x * 256 + threadIdx.x;
    float z0 = g_Zpart[0 * MTOT + s] + g_Zpart[1 * MTOT + s]
             + g_Zpart[2 * MTOT + s] + g_Zpart[3 * MTOT + s];
    float z1 = g_Zpart[4 * MTOT + s] + g_Zpart[5 * MTOT + s];
    float z2 = g_Zpart[6 * MTOT + s];
    float z3 = g_Zpart[7 * MTOT + s];
    float im = imp[s];
    *(float4*)(g_coef + s * 4) = make_float4(im / z0, im / z1, im / z2, im / z3);
}

// ---------------- K4: deterministic per-chunk accumulation (pure streaming) ----------
// grid (32 chunks, 8 batches); each block reduces 128 rows into w_part[b][chunk][960].
__global__ __launch_bounds__(256) void k_accum() {
    int b = blockIdx.y, c = blockIdx.x, t = threadIdx.x;
    float a0 = 0.f, a1 = 0.f, a2 = 0.f, a3 = 0.f;
    int base_s = b * S_ + c * 128;
#pragma unroll 4
    for (int r = 0; r < 128; r++) {
        int s = base_s + r;
        float4 cf = *(const float4*)(g_coef + s * 4);
        const float* Es = g_E + (size_t)s * NU;
        a0 += cf.x * Es[t];          // n in [0,256)    -> group 0
        a1 += cf.x * Es[t + 256];    // n in [256,512)  -> group 0
        a2 += cf.y * Es[t + 512];    // n in [512,768)  -> group 1
        if (t < 192) {
            float cg = (t < 128) ? cf.z : cf.w;  // [768,896)->g2, [896,960)->g3
            a3 += cg * Es[t + 768];
        }
    }
    float* wp = g_wpart + (size_t)(b * 32 + c) * NU;
    wp[t] = a0; wp[t + 256] = a1; wp[t + 512] = a2;
    if (t < 192) wp[t + 768] = a3;
}

// ---------------- K5: reduce partials + top-k + output formatting ----------------
// jax top_k tie-break: lowest index wins on equal values.
__device__ void warp_topk_mark(float* v, int size, int k) {
    unsigned lane = threadIdx.x & 31;
    for (int p = 0; p < k; p++) {
        float bv = -FLT_MAX; int bi = 0x7fffffff;
        for (int j = (int)lane; j < size; j += 32) {
            float val = v[j];
            if (val > bv) { bv = val; bi = j; }
        }
#pragma unroll
        for (int off = 16; off; off >>= 1) {
            float ov = __shfl_down_sync(0xffffffffu, bv, off);
            int   oi = __shfl_down_sync(0xffffffffu, bi, off);
            if (ov > bv || (ov == bv && oi < bi)) { bv = ov; bi = oi; }
        }
        bi = __shfl_sync(0xffffffffu, bi, 0);
        if (lane == 0) v[bi] = -FLT_MAX;   // sentinel mark (all real w > 0)
        __syncwarp();
    }
}

__global__ void k_final(float* __restrict__ out) {
    __shared__ float sw[NU];
    __shared__ float relv[128];
    __shared__ float valv[64];
    int b = blockIdx.x, t = threadIdx.x;
    for (int n = t; n < NU; n += 256) {
        float a = 0.f;
#pragma unroll
        for (int c = 0; c < 32; c++) a += g_wpart[(size_t)(b * 32 + c) * NU + n];
        sw[n] = a;
    }
    __syncthreads();
    if (t < 32) {
        for (int j = t; j < 128; j += 32) relv[j] = sw[768 + j];
        for (int j = t; j < 64;  j += 32) valv[j] = sw[896 + j];
        __syncwarp();
        warp_topk_mark(sw,        512, 64);   // qk indices
        warp_topk_mark(sw + 512,  256, 32);   // v  indices
        warp_topk_mark(sw + 768,  128, 16);   // rel sparse
        warp_topk_mark(sw + 896,   64,  3);   // val sparse
        if (t == 0) {
            int c = 0;
            for (int n = 0; n < 512; n++)
                if (sw[n] == -FLT_MAX) out[b * 64 + (c++)] = (float)n;        // idx_qk sorted
            c = 0;
            for (int n = 0; n < 256; n++)
                if (sw[512 + n] == -FLT_MAX) out[512 + b * 32 + (c++)] = (float)n;  // idx_v sorted
        }
        for (int n = t; n < 128; n += 32) {
            float val = (sw[768 + n] == -FLT_MAX) ? relv[n] : 0.f;
            out[768  + b * 128 + n] = val;   // rel_Q
            out[1792 + b * 128 + n] = val;   // rel_K (identical by construction)
        }
        for (int n = t; n < 64; n += 32) {
            float val = (sw[896 + n] == -FLT_MAX) ? valv[n] : 0.f;
            out[2816 + b * 64 + n] = val;    // val_w
        }
    }
}

// ---------------- launch ----------------
extern "C" void kernel_launch(void* const* d_in, const int* in_sizes, int n_in,
                              void* d_out, int out_size) {
    const float* x    = (const float*)d_in[0];
    const float* imp  = (const float*)d_in[1];
    const float* W    = (const float*)d_in[2];
    const float* bias = (const float*)d_in[3];
    const float* emb  = (const float*)d_in[4];
    float* out = (float*)d_out;

    k_norm<<<120, dim3(32, 8)>>>(emb);
    k_gemm1<<<MTOT / 128, 128>>>(x, W, bias);
    k_gemm2<<<dim3(MTOT / 128, 8), 256>>>();
    k_coef<<<MTOT / 256, 256>>>(imp);
    k_accum<<<dim3(32, B_), 256>>>();
    k_final<<<B_, 256>>>(out);
}

// round 7
// speedup vs baseline: 1.2845x; 1.1601x over previous
#include <cuda_runtime.h>
#include <cfloat>

// Problem constants
#define B_    8
#define S_    4096
#define D_    1024
#define DS_   64
#define MTOT  32768      // B_*S_
#define NU    960        // used neurons: 512+256+128+64 (N_KNOW unused)

// Scratch (device globals — allocation-free per harness rules)
__device__ float g_embn[NU * DS_];                 // normalized embeddings [960][64]
__device__ float g_E[(size_t)MTOT * NU];           // exp(logits) [32768][960]
__device__ float g_wpart[B_ * 32 * NU];            // per-chunk partial w [8][32][960]

// ---------------- f32x2 packed-FMA helpers ----------------
__device__ __forceinline__ unsigned long long pk2s(float a) {
    unsigned long long r;
    asm("mov.b64 %0, {%1, %1};" : "=l"(r) : "f"(a));
    return r;
}
__device__ __forceinline__ void fma2(unsigned long long& acc,
                                     unsigned long long a, unsigned long long b) {
    asm("fma.rn.f32x2 %0, %1, %2, %0;" : "+l"(acc) : "l"(a), "l"(b));
}
__device__ __forceinline__ float2 upk2(unsigned long long v) {
    float2 f;
    asm("mov.b64 {%0, %1}, %2;" : "=f"(f.x), "=f"(f.y) : "l"(v));
    return f;
}

// ---------------- K0: normalize neuron embeddings ----------------
__global__ void k_norm(const float* __restrict__ emb) {
    int lane = threadIdx.x;
    int n = blockIdx.x * 8 + threadIdx.y;
    if (n >= NU) return;
    float v0 = emb[n * 64 + lane];
    float v1 = emb[n * 64 + 32 + lane];
    float ss = v0 * v0 + v1 * v1;
#pragma unroll
    for (int off = 16; off; off >>= 1) ss += __shfl_xor_sync(0xffffffffu, ss, off);
    float inv = rsqrtf(ss);
    g_embn[n * 64 + lane]      = v0 * inv;
    g_embn[n * 64 + 32 + lane] = v1 * inv;
}

// ================= MEGA kernel =================
// Per block (256 thr), rows m0..m0+127:
//   Phase 1: h[128][64] = x@W^T + b, kept in smem (k-major)
//   Phase 2: for 8 n-slabs of 128: E = exp(h@embn^T) -> gmem; per-slab Z partials
//   Phase 3: coef = imp/Z (rows are block-local)
//   Phase 4: accum: wpart[bx][n] = sum_rows coef*E   (E re-read, L2-hot)
//
// Smem float offsets:
//   sh    [64][132]  @ 0       (8448)   h, k-major
//   sB    [64][132]  @ 8448    (8448)   embn slab, k-major  (phase2)
//     phase1 aliases: sAx[32][132] @ 8448, sW[32][68] @ 12672
//   sred  [128][17]  @ 16896   (2176)
//   szacc [128][4]   @ 19072   (512)
//   scoef [128][4]   @ 19584   (512)
#define SH_OFF    0
#define SB_OFF    8448
#define SAX_OFF   8448
#define SW_OFF    12672
#define SRED_OFF  16896
#define SZ_OFF    19072
#define SC_OFF    19584
#define SMEM_FLOATS 20096

__global__ __launch_bounds__(256, 2) void k_mega(const float* __restrict__ x,
                                                 const float* __restrict__ W,
                                                 const float* __restrict__ bias,
                                                 const float* __restrict__ imp) {
    extern __shared__ __align__(16) float sm[];
    float* sh    = sm + SH_OFF;
    float* sB    = sm + SB_OFF;
    float* sAx   = sm + SAX_OFF;
    float* sW    = sm + SW_OFF;
    float* sred  = sm + SRED_OFF;
    float* szacc = sm + SZ_OFF;
    float* scoef = sm + SC_OFF;

    int tid = threadIdx.x;
    int txn = tid & 15;             // 16 n-groups
    int tym = tid >> 4;             // 16 m-groups x 8 = 128
    int m0  = blockIdx.x * 128;

    if (tid < 128) {
#pragma unroll
        for (int g = 0; g < 4; g++) szacc[tid * 4 + g] = 0.f;
    }

    // ---------- Phase 1: h = x @ W^T + bias ----------
    {
        unsigned long long acc1[8][2];
#pragma unroll
        for (int i = 0; i < 8; i++) { acc1[i][0] = 0ull; acc1[i][1] = 0ull; }

        for (int kb = 0; kb < D_; kb += 32) {
            // x tile 128x32 -> sAx[k][m]
#pragma unroll
            for (int it = 0; it < 4; ++it) {
                int i = it * 256 + tid; int m = i >> 3; int c = i & 7;
                float4 v = *(const float4*)(x + (size_t)(m0 + m) * D_ + kb + c * 4);
                sAx[(c * 4 + 0) * 132 + m] = v.x; sAx[(c * 4 + 1) * 132 + m] = v.y;
                sAx[(c * 4 + 2) * 132 + m] = v.z; sAx[(c * 4 + 3) * 132 + m] = v.w;
            }
            // W tile 64x32 -> sW[k][n]
#pragma unroll
            for (int it = 0; it < 2; ++it) {
                int i = it * 256 + tid; int n = i >> 3; int c = i & 7;
                float4 v = *(const float4*)(W + (size_t)n * D_ + kb + c * 4);
                sW[(c * 4 + 0) * 68 + n] = v.x; sW[(c * 4 + 1) * 68 + n] = v.y;
                sW[(c * 4 + 2) * 68 + n] = v.z; sW[(c * 4 + 3) * 68 + n] = v.w;
            }
            __syncthreads();
#pragma unroll 8
            for (int kk = 0; kk < 32; ++kk) {
                float4 a0 = *(const float4*)&sAx[kk * 132 + tym * 8];
                float4 a1 = *(const float4*)&sAx[kk * 132 + tym * 8 + 4];
                ulonglong2 b = *(const ulonglong2*)&sW[kk * 68 + txn * 4]; // conflict-free
                float av[8] = { a0.x, a0.y, a0.z, a0.w, a1.x, a1.y, a1.z, a1.w };
#pragma unroll
                for (int i = 0; i < 8; i++) {
                    unsigned long long ad = pk2s(av[i]);
                    fma2(acc1[i][0], ad, b.x);
                    fma2(acc1[i][1], ad, b.y);
                }
            }
            __syncthreads();
        }
        // epilogue: + bias, transpose into sh[k][m]
        float b0 = bias[txn * 4 + 0], b1 = bias[txn * 4 + 1];
        float b2 = bias[txn * 4 + 2], b3 = bias[txn * 4 + 3];
#pragma unroll
        for (int i = 0; i < 8; i++) {
            int mloc = tym * 8 + i;
            float2 f0 = upk2(acc1[i][0]);
            float2 f1 = upk2(acc1[i][1]);
            sh[(txn * 4 + 0) * 132 + mloc] = f0.x + b0;
            sh[(txn * 4 + 1) * 132 + mloc] = f0.y + b1;
            sh[(txn * 4 + 2) * 132 + mloc] = f1.x + b2;
            sh[(txn * 4 + 3) * 132 + mloc] = f1.y + b3;
        }
        __syncthreads();
    }

    // ---------- Phase 2: E = exp(h @ embn^T) per 128-col slab; Z partials ----------
    for (int slab = 0; slab < 8; ++slab) {
        int n0 = slab * 128;
        // group of this slab (slab fits wholly in one group; boundaries 512/768/896)
        int g = (n0 < 512) ? 0 : (n0 < 768) ? 1 : (n0 < 896) ? 2 : 3;
        bool validB = (slab < 7);   // slab 7 upper half is n>=960 (unused)

        // load embn slab [128 n][64 k] -> sB[k][n]
#pragma unroll
        for (int it = 0; it < 8; ++it) {
            int i = it * 256 + tid; int n = i >> 4; int c = i & 15;
            float4 v = *(const float4*)(g_embn + (size_t)(n0 + n) * DS_ + c * 4);
            sB[(c * 4 + 0) * 132 + n] = v.x; sB[(c * 4 + 1) * 132 + n] = v.y;
            sB[(c * 4 + 2) * 132 + n] = v.z; sB[(c * 4 + 3) * 132 + n] = v.w;
        }
        __syncthreads();

        unsigned long long acc[8][4];
#pragma unroll
        for (int i = 0; i < 8; i++)
#pragma unroll
            for (int j = 0; j < 4; j++) acc[i][j] = 0ull;

#pragma unroll 8
        for (int kk = 0; kk < 64; ++kk) {
            float4 a0 = *(const float4*)&sh[kk * 132 + tym * 8];
            float4 a1 = *(const float4*)&sh[kk * 132 + tym * 8 + 4];
            // split n-tile: two float4s 64 apart -> conflict-free (quads 0..7 per phase)
            ulonglong2 bA = *(const ulonglong2*)&sB[kk * 132 + txn * 4];
            ulonglong2 bBv = *(const ulonglong2*)&sB[kk * 132 + 64 + txn * 4];
            float av[8] = { a0.x, a0.y, a0.z, a0.w, a1.x, a1.y, a1.z, a1.w };
#pragma unroll
            for (int i = 0; i < 8; i++) {
                unsigned long long ad = pk2s(av[i]);
                fma2(acc[i][0], ad, bA.x);
                fma2(acc[i][1], ad, bA.y);
                fma2(acc[i][2], ad, bBv.x);
                fma2(acc[i][3], ad, bBv.y);
            }
        }

        // epilogue: exp, store E, row sums
        float zrow[8];
#pragma unroll
        for (int i = 0; i < 8; i++) {
            int row = m0 + tym * 8 + i;
            float2 f0 = upk2(acc[i][0]), f1 = upk2(acc[i][1]);
            float eA0 = __expf(f0.x), eA1 = __expf(f0.y);
            float eA2 = __expf(f1.x), eA3 = __expf(f1.y);
            *(float4*)(g_E + (size_t)row * NU + n0 + txn * 4) = make_float4(eA0, eA1, eA2, eA3);
            float z = (eA0 + eA1) + (eA2 + eA3);
            if (validB) {
                float2 f2 = upk2(acc[i][2]), f3 = upk2(acc[i][3]);
                float eB0 = __expf(f2.x), eB1 = __expf(f2.y);
                float eB2 = __expf(f3.x), eB3 = __expf(f3.y);
                *(float4*)(g_E + (size_t)row * NU + n0 + 64 + txn * 4) =
                    make_float4(eB0, eB1, eB2, eB3);
                z += (eB0 + eB1) + (eB2 + eB3);
            }
            zrow[i] = z;
        }
        __syncthreads();   // sB reads done; sred safe
#pragma unroll
        for (int i = 0; i < 8; i++) sred[(tym * 8 + i) * 17 + txn] = zrow[i];
        __syncthreads();
        if (tid < 128) {
            float z = 0.f;
#pragma unroll
            for (int i = 0; i < 16; i++) z += sred[tid * 17 + i];
            szacc[tid * 4 + g] += z;
        }
        __syncthreads();   // szacc done; sB free for next slab
    }

    // ---------- Phase 3: coef = imp / Z ----------
    if (tid < 128) {
        float im = imp[m0 + tid];
#pragma unroll
        for (int g = 0; g < 4; g++) scoef[tid * 4 + g] = im / szacc[tid * 4 + g];
    }
    __syncthreads();   // also makes this block's g_E writes visible block-wide

    // ---------- Phase 4: accum -> wpart[bx][960] ----------
    {
        int t = tid;
        float a0 = 0.f, a1 = 0.f, a2 = 0.f, a3 = 0.f;
#pragma unroll 4
        for (int r = 0; r < 128; r++) {
            float4 cf = *(const float4*)(scoef + r * 4);
            const float* Es = g_E + (size_t)(m0 + r) * NU;
            a0 += cf.x * Es[t];          // [0,256)    g0
            a1 += cf.x * Es[t + 256];    // [256,512)  g0
            a2 += cf.y * Es[t + 512];    // [512,768)  g1
            if (t < 192) {
                float cg = (t < 128) ? cf.z : cf.w;  // [768,896) g2, [896,960) g3
                a3 += cg * Es[t + 768];
            }
        }
        float* wp = g_wpart + (size_t)blockIdx.x * NU;
        wp[t] = a0; wp[t + 256] = a1; wp[t + 512] = a2;
        if (t < 192) wp[t + 768] = a3;
    }
}

// ---------------- K5: reduce partials + top-k + output formatting ----------------
__device__ void warp_topk_mark(float* v, int size, int k) {
    unsigned lane = threadIdx.x & 31;
    for (int p = 0; p < k; p++) {
        float bv = -FLT_MAX; int bi = 0x7fffffff;
        for (int j = (int)lane; j < size; j += 32) {
            float val = v[j];
            if (val > bv) { bv = val; bi = j; }
        }
#pragma unroll
        for (int off = 16; off; off >>= 1) {
            float ov = __shfl_down_sync(0xffffffffu, bv, off);
            int   oi = __shfl_down_sync(0xffffffffu, bi, off);
            if (ov > bv || (ov == bv && oi < bi)) { bv = ov; bi = oi; }
        }
        bi = __shfl_sync(0xffffffffu, bi, 0);
        if (lane == 0) v[bi] = -FLT_MAX;
        __syncwarp();
    }
}

__global__ void k_final(float* __restrict__ out) {
    __shared__ float sw[NU];
    __shared__ float relv[128];
    __shared__ float valv[64];
    int b = blockIdx.x, t = threadIdx.x;
    for (int n = t; n < NU; n += 256) {
        float a = 0.f;
#pragma unroll
        for (int c = 0; c < 32; c++) a += g_wpart[(size_t)(b * 32 + c) * NU + n];
        sw[n] = a;
    }
    __syncthreads();
    if (t < 32) {
        for (int j = t; j < 128; j += 32) relv[j] = sw[768 + j];
        for (int j = t; j < 64;  j += 32) valv[j] = sw[896 + j];
        __syncwarp();
        warp_topk_mark(sw,        512, 64);
        warp_topk_mark(sw + 512,  256, 32);
        warp_topk_mark(sw + 768,  128, 16);
        warp_topk_mark(sw + 896,   64,  3);
        if (t == 0) {
            int c = 0;
            for (int n = 0; n < 512; n++)
                if (sw[n] == -FLT_MAX) out[b * 64 + (c++)] = (float)n;
            c = 0;
            for (int n = 0; n < 256; n++)
                if (sw[512 + n] == -FLT_MAX) out[512 + b * 32 + (c++)] = (float)n;
        }
        for (int n = t; n < 128; n += 32) {
            float val = (sw[768 + n] == -FLT_MAX) ? relv[n] : 0.f;
            out[768  + b * 128 + n] = val;   // rel_Q
            out[1792 + b * 128 + n] = val;   // rel_K
        }
        for (int n = t; n < 64; n += 32) {
            float val = (sw[896 + n] == -FLT_MAX) ? valv[n] : 0.f;
            out[2816 + b * 64 + n] = val;    // val_w
        }
    }
}

// ---------------- launch ----------------
extern "C" void kernel_launch(void* const* d_in, const int* in_sizes, int n_in,
                              void* d_out, int out_size) {
    const float* x    = (const float*)d_in[0];
    const float* imp  = (const float*)d_in[1];
    const float* W    = (const float*)d_in[2];
    const float* bias = (const float*)d_in[3];
    const float* emb  = (const float*)d_in[4];
    float* out = (float*)d_out;

    static bool attr_set = false;
    if (!attr_set) {
        cudaFuncSetAttribute(k_mega, cudaFuncAttributeMaxDynamicSharedMemorySize,
                             SMEM_FLOATS * 4);
        attr_set = true;
    }

    k_norm<<<120, dim3(32, 8)>>>(emb);
    k_mega<<<MTOT / 128, 256, SMEM_FLOATS * 4>>>(x, W, bias, imp);
    k_final<<<B_, 256>>>(out);
}

// round 8
// speedup vs baseline: 1.2959x; 1.0089x over previous
#include <cuda_runtime.h>
#include <cfloat>

// Problem constants
#define B_    8
#define S_    4096
#define D_    1024
#define DS_   64
#define MTOT  32768      // B_*S_
#define NU    960        // used neurons: 512+256+128+64 (N_KNOW unused)

// Scratch (device globals — allocation-free per harness rules)
__device__ float g_E[(size_t)MTOT * NU];           // exp(logits) [32768][960]
__device__ float g_wpart[256 * NU];                // per-block partial w [256][960]

// ---------------- f32x2 packed-FMA helpers ----------------
__device__ __forceinline__ unsigned long long pk2s(float a) {
    unsigned long long r;
    asm("mov.b64 %0, {%1, %1};" : "=l"(r) : "f"(a));
    return r;
}
__device__ __forceinline__ void fma2(unsigned long long& acc,
                                     unsigned long long a, unsigned long long b) {
    asm("fma.rn.f32x2 %0, %1, %2, %0;" : "+l"(acc) : "l"(a), "l"(b));
}
__device__ __forceinline__ float2 upk2(unsigned long long v) {
    float2 f;
    asm("mov.b64 {%0, %1}, %2;" : "=f"(f.x), "=f"(f.y) : "l"(v));
    return f;
}

// Smem float offsets:
//   sh    [64][132]   @ 0      (8448)  h, k-major
//   sB    [64][132]   @ 8448   (8448)  embn slab (phase2) | aliases phase1 tiles:
//     sAx [32][132]   @ 8448,  sW [32][68] @ 12672
//   sred  [2][128][17]@ 16896  (4352)  ping-pong row-sum reduce
//   szacc [128][4]    @ 21248  (512)
//   scoef [128][4]    @ 21760  (512)
//   snorm [960]       @ 22272  (960)
#define SH_OFF    0
#define SB_OFF    8448
#define SAX_OFF   8448
#define SW_OFF    12672
#define SRED_OFF  16896
#define SZ_OFF    21248
#define SC_OFF    21760
#define SN_OFF    22272
#define SMEM_FLOATS 23232

__global__ __launch_bounds__(256, 2) void k_mega(const float* __restrict__ x,
                                                 const float* __restrict__ W,
                                                 const float* __restrict__ bias,
                                                 const float* __restrict__ imp,
                                                 const float* __restrict__ emb) {
    extern __shared__ __align__(16) float sm[];
    float* sh    = sm + SH_OFF;
    float* sB    = sm + SB_OFF;
    float* sAx   = sm + SAX_OFF;
    float* sW    = sm + SW_OFF;
    float* sred  = sm + SRED_OFF;
    float* szacc = sm + SZ_OFF;
    float* scoef = sm + SC_OFF;
    float* snorm = sm + SN_OFF;

    int tid = threadIdx.x;
    int txn = tid & 15;             // 16 n-groups
    int tym = tid >> 4;             // 16 m-groups x 8 = 128
    int m0  = blockIdx.x * 128;

    // ---- embedding inverse norms (fused; replaces k_norm launch) ----
    for (int n = tid; n < NU; n += 256) {
        const float4* er = (const float4*)(emb + (size_t)n * DS_);
        float ss = 0.f;
#pragma unroll
        for (int j = 0; j < 16; j++) {
            float4 v = er[j];
            ss += v.x * v.x + v.y * v.y + v.z * v.z + v.w * v.w;
        }
        snorm[n] = rsqrtf(ss);
    }
    if (tid < 128) {
#pragma unroll
        for (int g = 0; g < 4; g++) szacc[tid * 4 + g] = 0.f;
    }
    // (visibility of snorm/szacc guaranteed by phase-1 barriers before use)

    // ---------- Phase 1: h = x @ W^T + bias (register double-buffered) ----------
    {
        unsigned long long acc1[8][2];
#pragma unroll
        for (int i = 0; i < 8; i++) { acc1[i][0] = 0ull; acc1[i][1] = 0ull; }

        float4 xv[4], wv[2];
#pragma unroll
        for (int it = 0; it < 4; ++it) {
            int i = it * 256 + tid; int m = i >> 3; int c = i & 7;
            xv[it] = *(const float4*)(x + (size_t)(m0 + m) * D_ + c * 4);
        }
#pragma unroll
        for (int it = 0; it < 2; ++it) {
            int i = it * 256 + tid; int n = i >> 3; int c = i & 7;
            wv[it] = *(const float4*)(W + (size_t)n * D_ + c * 4);
        }

        for (int kb = 0; kb < D_; kb += 32) {
            // commit current tile to smem
#pragma unroll
            for (int it = 0; it < 4; ++it) {
                int i = it * 256 + tid; int m = i >> 3; int c = i & 7;
                sAx[(c * 4 + 0) * 132 + m] = xv[it].x; sAx[(c * 4 + 1) * 132 + m] = xv[it].y;
                sAx[(c * 4 + 2) * 132 + m] = xv[it].z; sAx[(c * 4 + 3) * 132 + m] = xv[it].w;
            }
#pragma unroll
            for (int it = 0; it < 2; ++it) {
                int i = it * 256 + tid; int n = i >> 3; int c = i & 7;
                sW[(c * 4 + 0) * 68 + n] = wv[it].x; sW[(c * 4 + 1) * 68 + n] = wv[it].y;
                sW[(c * 4 + 2) * 68 + n] = wv[it].z; sW[(c * 4 + 3) * 68 + n] = wv[it].w;
            }
            __syncthreads();
            // prefetch next tile (overlaps with compute below)
            if (kb + 32 < D_) {
#pragma unroll
                for (int it = 0; it < 4; ++it) {
                    int i = it * 256 + tid; int m = i >> 3; int c = i & 7;
                    xv[it] = *(const float4*)(x + (size_t)(m0 + m) * D_ + kb + 32 + c * 4);
                }
#pragma unroll
                for (int it = 0; it < 2; ++it) {
                    int i = it * 256 + tid; int n = i >> 3; int c = i & 7;
                    wv[it] = *(const float4*)(W + (size_t)n * D_ + kb + 32 + c * 4);
                }
            }
#pragma unroll 8
            for (int kk = 0; kk < 32; ++kk) {
                float4 a0 = *(const float4*)&sAx[kk * 132 + tym * 8];
                float4 a1 = *(const float4*)&sAx[kk * 132 + tym * 8 + 4];
                ulonglong2 b = *(const ulonglong2*)&sW[kk * 68 + txn * 4];
                float av[8] = { a0.x, a0.y, a0.z, a0.w, a1.x, a1.y, a1.z, a1.w };
#pragma unroll
                for (int i = 0; i < 8; i++) {
                    unsigned long long ad = pk2s(av[i]);
                    fma2(acc1[i][0], ad, b.x);
                    fma2(acc1[i][1], ad, b.y);
                }
            }
            __syncthreads();   // smem tiles free for next commit
        }
        // epilogue: + bias, transpose into sh[k][m]
        float b0 = bias[txn * 4 + 0], b1 = bias[txn * 4 + 1];
        float b2 = bias[txn * 4 + 2], b3 = bias[txn * 4 + 3];
#pragma unroll
        for (int i = 0; i < 8; i++) {
            int mloc = tym * 8 + i;
            float2 f0 = upk2(acc1[i][0]);
            float2 f1 = upk2(acc1[i][1]);
            sh[(txn * 4 + 0) * 132 + mloc] = f0.x + b0;
            sh[(txn * 4 + 1) * 132 + mloc] = f0.y + b1;
            sh[(txn * 4 + 2) * 132 + mloc] = f1.x + b2;
            sh[(txn * 4 + 3) * 132 + mloc] = f1.y + b3;
        }
        __syncthreads();
    }

    // ---------- Phase 2: E = exp(h @ embn^T); slabs 0..6 full 128 cols ----------
    for (int slab = 0; slab < 7; ++slab) {
        int n0 = slab * 128;
        int g  = (slab < 4) ? 0 : (slab < 6) ? 1 : 2;   // group of this slab
        float* sred_s = sred + (slab & 1) * 2176;

        // load embn slab [128 n][64 k] -> sB[k][n], scaled by 1/||emb_n|| on the fly
#pragma unroll
        for (int it = 0; it < 8; ++it) {
            int i = it * 256 + tid; int n = i >> 4; int c = i & 15;
            float s = snorm[n0 + n];
            float4 v = *(const float4*)(emb + (size_t)(n0 + n) * DS_ + c * 4);
            sB[(c * 4 + 0) * 132 + n] = v.x * s; sB[(c * 4 + 1) * 132 + n] = v.y * s;
            sB[(c * 4 + 2) * 132 + n] = v.z * s; sB[(c * 4 + 3) * 132 + n] = v.w * s;
        }
        __syncthreads();   // sB ready

        unsigned long long acc[8][4];
#pragma unroll
        for (int i = 0; i < 8; i++)
#pragma unroll
            for (int j = 0; j < 4; j++) acc[i][j] = 0ull;

#pragma unroll 8
        for (int kk = 0; kk < 64; ++kk) {
            float4 a0 = *(const float4*)&sh[kk * 132 + tym * 8];
            float4 a1 = *(const float4*)&sh[kk * 132 + tym * 8 + 4];
            ulonglong2 bA = *(const ulonglong2*)&sB[kk * 132 + txn * 4];
            ulonglong2 bBv = *(const ulonglong2*)&sB[kk * 132 + 64 + txn * 4];
            float av[8] = { a0.x, a0.y, a0.z, a0.w, a1.x, a1.y, a1.z, a1.w };
#pragma unroll
            for (int i = 0; i < 8; i++) {
                unsigned long long ad = pk2s(av[i]);
                fma2(acc[i][0], ad, bA.x);
                fma2(acc[i][1], ad, bA.y);
                fma2(acc[i][2], ad, bBv.x);
                fma2(acc[i][3], ad, bBv.y);
            }
        }

        // epilogue: exp, store E, row sums -> sred (disjoint region, no sync needed)
#pragma unroll
        for (int i = 0; i < 8; i++) {
            int row = m0 + tym * 8 + i;
            float2 f0 = upk2(acc[i][0]), f1 = upk2(acc[i][1]);
            float2 f2 = upk2(acc[i][2]), f3 = upk2(acc[i][3]);
            float eA0 = __expf(f0.x), eA1 = __expf(f0.y);
            float eA2 = __expf(f1.x), eA3 = __expf(f1.y);
            float eB0 = __expf(f2.x), eB1 = __expf(f2.y);
            float eB2 = __expf(f3.x), eB3 = __expf(f3.y);
            *(float4*)(g_E + (size_t)row * NU + n0 + txn * 4)      = make_float4(eA0, eA1, eA2, eA3);
            *(float4*)(g_E + (size_t)row * NU + n0 + 64 + txn * 4) = make_float4(eB0, eB1, eB2, eB3);
            sred_s[(tym * 8 + i) * 17 + txn] =
                ((eA0 + eA1) + (eA2 + eA3)) + ((eB0 + eB1) + (eB2 + eB3));
        }
        __syncthreads();   // sred complete AND all sB reads done
        if (tid < 128) {   // reduce overlaps next slab's loads (ping-pong sred)
            float z = 0.f;
#pragma unroll
            for (int i = 0; i < 16; i++) z += sred_s[tid * 17 + i];
            szacc[tid * 4 + g] += z;
        }
    }

    // ---------- slab 7: n0=896, 64 live cols, group 3 ----------
    {
        const int n0 = 896;
        float* sred_s = sred + 2176;   // slab index 7 -> odd buffer
#pragma unroll
        for (int it = 0; it < 4; ++it) {
            int i = it * 256 + tid; int n = i >> 4; int c = i & 15;
            float s = snorm[n0 + n];
            float4 v = *(const float4*)(emb + (size_t)(n0 + n) * DS_ + c * 4);
            sB[(c * 4 + 0) * 132 + n] = v.x * s; sB[(c * 4 + 1) * 132 + n] = v.y * s;
            sB[(c * 4 + 2) * 132 + n] = v.z * s; sB[(c * 4 + 3) * 132 + n] = v.w * s;
        }
        __syncthreads();

        unsigned long long acc[8][2];
#pragma unroll
        for (int i = 0; i < 8; i++) { acc[i][0] = 0ull; acc[i][1] = 0ull; }
#pragma unroll 8
        for (int kk = 0; kk < 64; ++kk) {
            float4 a0 = *(const float4*)&sh[kk * 132 + tym * 8];
            float4 a1 = *(const float4*)&sh[kk * 132 + tym * 8 + 4];
            ulonglong2 bA = *(const ulonglong2*)&sB[kk * 132 + txn * 4];
            float av[8] = { a0.x, a0.y, a0.z, a0.w, a1.x, a1.y, a1.z, a1.w };
#pragma unroll
            for (int i = 0; i < 8; i++) {
                unsigned long long ad = pk2s(av[i]);
                fma2(acc[i][0], ad, bA.x);
                fma2(acc[i][1], ad, bA.y);
            }
        }
#pragma unroll
        for (int i = 0; i < 8; i++) {
            int row = m0 + tym * 8 + i;
            float2 f0 = upk2(acc[i][0]), f1 = upk2(acc[i][1]);
            float e0 = __expf(f0.x), e1 = __expf(f0.y);
            float e2 = __expf(f1.x), e3 = __expf(f1.y);
            *(float4*)(g_E + (size_t)row * NU + n0 + txn * 4) = make_float4(e0, e1, e2, e3);
            sred_s[(tym * 8 + i) * 17 + txn] = (e0 + e1) + (e2 + e3);
        }
        __syncthreads();
        if (tid < 128) {
            float z = 0.f;
#pragma unroll
            for (int i = 0; i < 16; i++) z += sred_s[tid * 17 + i];
            szacc[tid * 4 + 3] += z;
        }
        __syncthreads();   // szacc complete for phase 3
    }

    // ---------- Phase 3: coef = imp / Z ----------
    if (tid < 128) {
        float im = imp[m0 + tid];
#pragma unroll
        for (int g = 0; g < 4; g++) scoef[tid * 4 + g] = im * __frcp_rn(szacc[tid * 4 + g]);
    }
    __syncthreads();   // also: this block's g_E writes visible block-wide

    // ---------- Phase 4: accum -> wpart[bx][960] (vectorized) ----------
    if (tid < 240) {
        int n4 = tid * 4;
        int g = (n4 < 512) ? 0 : (n4 < 768) ? 1 : (n4 < 896) ? 2 : 3;
        float4 a = make_float4(0.f, 0.f, 0.f, 0.f);
#pragma unroll 4
        for (int r = 0; r < 128; r++) {
            float cf = scoef[r * 4 + g];
            float4 e = *(const float4*)(g_E + (size_t)(m0 + r) * NU + n4);
            a.x += cf * e.x; a.y += cf * e.y; a.z += cf * e.z; a.w += cf * e.w;
        }
        *(float4*)(g_wpart + (size_t)blockIdx.x * NU + n4) = a;
    }
}

// ---------------- k_final: reduce partials + top-k + output formatting ----------------
__device__ void warp_topk_mark(float* v, int size, int k) {
    unsigned lane = threadIdx.x & 31;
    for (int p = 0; p < k; p++) {
        float bv = -FLT_MAX; int bi = 0x7fffffff;
        for (int j = (int)lane; j < size; j += 32) {
            float val = v[j];
            if (val > bv) { bv = val; bi = j; }
        }
#pragma unroll
        for (int off = 16; off; off >>= 1) {
            float ov = __shfl_down_sync(0xffffffffu, bv, off);
            int   oi = __shfl_down_sync(0xffffffffu, bi, off);
            if (ov > bv || (ov == bv && oi < bi)) { bv = ov; bi = oi; }
        }
        bi = __shfl_sync(0xffffffffu, bi, 0);
        if (lane == 0) v[bi] = -FLT_MAX;
        __syncwarp();
    }
}

__global__ void k_final(float* __restrict__ out) {
    __shared__ float sw[NU];
    __shared__ float relv[128];
    __shared__ float valv[64];
    int b = blockIdx.x, t = threadIdx.x;
    for (int n = t; n < NU; n += 256) {
        float a = 0.f;
#pragma unroll
        for (int c = 0; c < 32; c++) a += g_wpart[(size_t)(b * 32 + c) * NU + n];
        sw[n] = a;
    }
    __syncthreads();
    if (t < 32) {
        for (int j = t; j < 128; j += 32) relv[j] = sw[768 + j];
        for (int j = t; j < 64;  j += 32) valv[j] = sw[896 + j];
        __syncwarp();
        warp_topk_mark(sw,        512, 64);
        warp_topk_mark(sw + 512,  256, 32);
        warp_topk_mark(sw + 768,  128, 16);
        warp_topk_mark(sw + 896,   64,  3);
        if (t == 0) {
            int c = 0;
            for (int n = 0; n < 512; n++)
                if (sw[n] == -FLT_MAX) out[b * 64 + (c++)] = (float)n;
            c = 0;
            for (int n = 0; n < 256; n++)
                if (sw[512 + n] == -FLT_MAX) out[512 + b * 32 + (c++)] = (float)n;
        }
        for (int n = t; n < 128; n += 32) {
            float val = (sw[768 + n] == -FLT_MAX) ? relv[n] : 0.f;
            out[768  + b * 128 + n] = val;   // rel_Q
            out[1792 + b * 128 + n] = val;   // rel_K
        }
        for (int n = t; n < 64; n += 32) {
            float val = (sw[896 + n] == -FLT_MAX) ? valv[n] : 0.f;
            out[2816 + b * 64 + n] = val;    // val_w
        }
    }
}

// ---------------- launch ----------------
extern "C" void kernel_launch(void* const* d_in, const int* in_sizes, int n_in,
                              void* d_out, int out_size) {
    const float* x    = (const float*)d_in[0];
    const float* imp  = (const float*)d_in[1];
    const float* W    = (const float*)d_in[2];
    const float* bias = (const float*)d_in[3];
    const float* emb  = (const float*)d_in[4];
    float* out = (float*)d_out;

    static bool attr_set = false;
    if (!attr_set) {
        cudaFuncSetAttribute(k_mega, cudaFuncAttributeMaxDynamicSharedMemorySize,
                             SMEM_FLOATS * 4);
        attr_set = true;
    }

    k_mega<<<MTOT / 128, 256, SMEM_FLOATS * 4>>>(x, W, bias, imp, emb);
    k_final<<<B_, 256>>>(out);
}

// round 9
// speedup vs baseline: 1.4908x; 1.1504x over previous
#include <cuda_runtime.h>
#include <cfloat>

// Problem constants
#define B_    8
#define S_    4096
#define D_    1024
#define DS_   64
#define MTOT  32768      // B_*S_
#define NU    960        // used neurons: 512+256+128+64 (N_KNOW unused)

// Scratch (device globals — allocation-free per harness rules)
__device__ float g_E[(size_t)MTOT * NU];           // exp(logits) [32768][960]
__device__ float g_wpart[256 * NU];                // per-block partial w [256][960]

// ---------------- f32x2 packed-FMA helpers ----------------
__device__ __forceinline__ unsigned long long pk2s(float a) {
    unsigned long long r;
    asm("mov.b64 %0, {%1, %1};" : "=l"(r) : "f"(a));
    return r;
}
__device__ __forceinline__ void fma2(unsigned long long& acc,
                                     unsigned long long a, unsigned long long b) {
    asm("fma.rn.f32x2 %0, %1, %2, %0;" : "+l"(acc) : "l"(a), "l"(b));
}
__device__ __forceinline__ float2 upk2(unsigned long long v) {
    float2 f;
    asm("mov.b64 {%0, %1}, %2;" : "=f"(f.x), "=f"(f.y) : "l"(v));
    return f;
}

// Smem float offsets (k_mega):
#define SH_OFF    0
#define SB_OFF    8448
#define SAX_OFF   8448
#define SW_OFF    12672
#define SRED_OFF  16896
#define SZ_OFF    21248
#define SC_OFF    21760
#define SN_OFF    22272
#define SMEM_FLOATS 23232

__global__ __launch_bounds__(256, 2) void k_mega(const float* __restrict__ x,
                                                 const float* __restrict__ W,
                                                 const float* __restrict__ bias,
                                                 const float* __restrict__ imp,
                                                 const float* __restrict__ emb) {
    extern __shared__ __align__(16) float sm[];
    float* sh    = sm + SH_OFF;
    float* sB    = sm + SB_OFF;
    float* sAx   = sm + SAX_OFF;
    float* sW    = sm + SW_OFF;
    float* sred  = sm + SRED_OFF;
    float* szacc = sm + SZ_OFF;
    float* scoef = sm + SC_OFF;
    float* snorm = sm + SN_OFF;

    int tid = threadIdx.x;
    int txn = tid & 15;             // 16 n-groups
    int tym = tid >> 4;             // 16 m-groups x 8 = 128
    int m0  = blockIdx.x * 128;

    // ---- embedding inverse norms (fused) ----
    for (int n = tid; n < NU; n += 256) {
        const float4* er = (const float4*)(emb + (size_t)n * DS_);
        float ss = 0.f;
#pragma unroll
        for (int j = 0; j < 16; j++) {
            float4 v = er[j];
            ss += v.x * v.x + v.y * v.y + v.z * v.z + v.w * v.w;
        }
        snorm[n] = rsqrtf(ss);
    }
    if (tid < 128) {
#pragma unroll
        for (int g = 0; g < 4; g++) szacc[tid * 4 + g] = 0.f;
    }

    // ---------- Phase 1: h = x @ W^T + bias (register double-buffered) ----------
    {
        unsigned long long acc1[8][2];
#pragma unroll
        for (int i = 0; i < 8; i++) { acc1[i][0] = 0ull; acc1[i][1] = 0ull; }

        float4 xv[4], wv[2];
#pragma unroll
        for (int it = 0; it < 4; ++it) {
            int i = it * 256 + tid; int m = i >> 3; int c = i & 7;
            xv[it] = *(const float4*)(x + (size_t)(m0 + m) * D_ + c * 4);
        }
#pragma unroll
        for (int it = 0; it < 2; ++it) {
            int i = it * 256 + tid; int n = i >> 3; int c = i & 7;
            wv[it] = *(const float4*)(W + (size_t)n * D_ + c * 4);
        }

        for (int kb = 0; kb < D_; kb += 32) {
#pragma unroll
            for (int it = 0; it < 4; ++it) {
                int i = it * 256 + tid; int m = i >> 3; int c = i & 7;
                sAx[(c * 4 + 0) * 132 + m] = xv[it].x; sAx[(c * 4 + 1) * 132 + m] = xv[it].y;
                sAx[(c * 4 + 2) * 132 + m] = xv[it].z; sAx[(c * 4 + 3) * 132 + m] = xv[it].w;
            }
#pragma unroll
            for (int it = 0; it < 2; ++it) {
                int i = it * 256 + tid; int n = i >> 3; int c = i & 7;
                sW[(c * 4 + 0) * 68 + n] = wv[it].x; sW[(c * 4 + 1) * 68 + n] = wv[it].y;
                sW[(c * 4 + 2) * 68 + n] = wv[it].z; sW[(c * 4 + 3) * 68 + n] = wv[it].w;
            }
            __syncthreads();
            if (kb + 32 < D_) {
#pragma unroll
                for (int it = 0; it < 4; ++it) {
                    int i = it * 256 + tid; int m = i >> 3; int c = i & 7;
                    xv[it] = *(const float4*)(x + (size_t)(m0 + m) * D_ + kb + 32 + c * 4);
                }
#pragma unroll
                for (int it = 0; it < 2; ++it) {
                    int i = it * 256 + tid; int n = i >> 3; int c = i & 7;
                    wv[it] = *(const float4*)(W + (size_t)n * D_ + kb + 32 + c * 4);
                }
            }
#pragma unroll 8
            for (int kk = 0; kk < 32; ++kk) {
                float4 a0 = *(const float4*)&sAx[kk * 132 + tym * 8];
                float4 a1 = *(const float4*)&sAx[kk * 132 + tym * 8 + 4];
                ulonglong2 b = *(const ulonglong2*)&sW[kk * 68 + txn * 4];
                float av[8] = { a0.x, a0.y, a0.z, a0.w, a1.x, a1.y, a1.z, a1.w };
#pragma unroll
                for (int i = 0; i < 8; i++) {
                    unsigned long long ad = pk2s(av[i]);
                    fma2(acc1[i][0], ad, b.x);
                    fma2(acc1[i][1], ad, b.y);
                }
            }
            __syncthreads();
        }
        float b0 = bias[txn * 4 + 0], b1 = bias[txn * 4 + 1];
        float b2 = bias[txn * 4 + 2], b3 = bias[txn * 4 + 3];
#pragma unroll
        for (int i = 0; i < 8; i++) {
            int mloc = tym * 8 + i;
            float2 f0 = upk2(acc1[i][0]);
            float2 f1 = upk2(acc1[i][1]);
            sh[(txn * 4 + 0) * 132 + mloc] = f0.x + b0;
            sh[(txn * 4 + 1) * 132 + mloc] = f0.y + b1;
            sh[(txn * 4 + 2) * 132 + mloc] = f1.x + b2;
            sh[(txn * 4 + 3) * 132 + mloc] = f1.y + b3;
        }
        __syncthreads();
    }

    // ---------- Phase 2: E = exp(h @ embn^T); slabs 0..6 full 128 cols ----------
    for (int slab = 0; slab < 7; ++slab) {
        int n0 = slab * 128;
        int g  = (slab < 4) ? 0 : (slab < 6) ? 1 : 2;
        float* sred_s = sred + (slab & 1) * 2176;

#pragma unroll
        for (int it = 0; it < 8; ++it) {
            int i = it * 256 + tid; int n = i >> 4; int c = i & 15;
            float s = snorm[n0 + n];
            float4 v = *(const float4*)(emb + (size_t)(n0 + n) * DS_ + c * 4);
            sB[(c * 4 + 0) * 132 + n] = v.x * s; sB[(c * 4 + 1) * 132 + n] = v.y * s;
            sB[(c * 4 + 2) * 132 + n] = v.z * s; sB[(c * 4 + 3) * 132 + n] = v.w * s;
        }
        __syncthreads();

        unsigned long long acc[8][4];
#pragma unroll
        for (int i = 0; i < 8; i++)
#pragma unroll
            for (int j = 0; j < 4; j++) acc[i][j] = 0ull;

#pragma unroll 8
        for (int kk = 0; kk < 64; ++kk) {
            float4 a0 = *(const float4*)&sh[kk * 132 + tym * 8];
            float4 a1 = *(const float4*)&sh[kk * 132 + tym * 8 + 4];
            ulonglong2 bA = *(const ulonglong2*)&sB[kk * 132 + txn * 4];
            ulonglong2 bBv = *(const ulonglong2*)&sB[kk * 132 + 64 + txn * 4];
            float av[8] = { a0.x, a0.y, a0.z, a0.w, a1.x, a1.y, a1.z, a1.w };
#pragma unroll
            for (int i = 0; i < 8; i++) {
                unsigned long long ad = pk2s(av[i]);
                fma2(acc[i][0], ad, bA.x);
                fma2(acc[i][1], ad, bA.y);
                fma2(acc[i][2], ad, bBv.x);
                fma2(acc[i][3], ad, bBv.y);
            }
        }

#pragma unroll
        for (int i = 0; i < 8; i++) {
            int row = m0 + tym * 8 + i;
            float2 f0 = upk2(acc[i][0]), f1 = upk2(acc[i][1]);
            float2 f2 = upk2(acc[i][2]), f3 = upk2(acc[i][3]);
            float eA0 = __expf(f0.x), eA1 = __expf(f0.y);
            float eA2 = __expf(f1.x), eA3 = __expf(f1.y);
            float eB0 = __expf(f2.x), eB1 = __expf(f2.y);
            float eB2 = __expf(f3.x), eB3 = __expf(f3.y);
            *(float4*)(g_E + (size_t)row * NU + n0 + txn * 4)      = make_float4(eA0, eA1, eA2, eA3);
            *(float4*)(g_E + (size_t)row * NU + n0 + 64 + txn * 4) = make_float4(eB0, eB1, eB2, eB3);
            sred_s[(tym * 8 + i) * 17 + txn] =
                ((eA0 + eA1) + (eA2 + eA3)) + ((eB0 + eB1) + (eB2 + eB3));
        }
        __syncthreads();
        if (tid < 128) {
            float z = 0.f;
#pragma unroll
            for (int i = 0; i < 16; i++) z += sred_s[tid * 17 + i];
            szacc[tid * 4 + g] += z;
        }
    }

    // ---------- slab 7: n0=896, 64 live cols, group 3 ----------
    {
        const int n0 = 896;
        float* sred_s = sred + 2176;
#pragma unroll
        for (int it = 0; it < 4; ++it) {
            int i = it * 256 + tid; int n = i >> 4; int c = i & 15;
            float s = snorm[n0 + n];
            float4 v = *(const float4*)(emb + (size_t)(n0 + n) * DS_ + c * 4);
            sB[(c * 4 + 0) * 132 + n] = v.x * s; sB[(c * 4 + 1) * 132 + n] = v.y * s;
            sB[(c * 4 + 2) * 132 + n] = v.z * s; sB[(c * 4 + 3) * 132 + n] = v.w * s;
        }
        __syncthreads();

        unsigned long long acc[8][2];
#pragma unroll
        for (int i = 0; i < 8; i++) { acc[i][0] = 0ull; acc[i][1] = 0ull; }
#pragma unroll 8
        for (int kk = 0; kk < 64; ++kk) {
            float4 a0 = *(const float4*)&sh[kk * 132 + tym * 8];
            float4 a1 = *(const float4*)&sh[kk * 132 + tym * 8 + 4];
            ulonglong2 bA = *(const ulonglong2*)&sB[kk * 132 + txn * 4];
            float av[8] = { a0.x, a0.y, a0.z, a0.w, a1.x, a1.y, a1.z, a1.w };
#pragma unroll
            for (int i = 0; i < 8; i++) {
                unsigned long long ad = pk2s(av[i]);
                fma2(acc[i][0], ad, bA.x);
                fma2(acc[i][1], ad, bA.y);
            }
        }
#pragma unroll
        for (int i = 0; i < 8; i++) {
            int row = m0 + tym * 8 + i;
            float2 f0 = upk2(acc[i][0]), f1 = upk2(acc[i][1]);
            float e0 = __expf(f0.x), e1 = __expf(f0.y);
            float e2 = __expf(f1.x), e3 = __expf(f1.y);
            *(float4*)(g_E + (size_t)row * NU + n0 + txn * 4) = make_float4(e0, e1, e2, e3);
            sred_s[(tym * 8 + i) * 17 + txn] = (e0 + e1) + (e2 + e3);
        }
        __syncthreads();
        if (tid < 128) {
            float z = 0.f;
#pragma unroll
            for (int i = 0; i < 16; i++) z += sred_s[tid * 17 + i];
            szacc[tid * 4 + 3] += z;
        }
        __syncthreads();
    }

    // ---------- Phase 3: coef = imp / Z ----------
    if (tid < 128) {
        float im = imp[m0 + tid];
#pragma unroll
        for (int g = 0; g < 4; g++) scoef[tid * 4 + g] = im * __frcp_rn(szacc[tid * 4 + g]);
    }
    __syncthreads();

    // ---------- Phase 4: accum -> wpart[bx][960] ----------
    if (tid < 240) {
        int n4 = tid * 4;
        int g = (n4 < 512) ? 0 : (n4 < 768) ? 1 : (n4 < 896) ? 2 : 3;
        float4 a = make_float4(0.f, 0.f, 0.f, 0.f);
#pragma unroll 4
        for (int r = 0; r < 128; r++) {
            float cf = scoef[r * 4 + g];
            float4 e = *(const float4*)(g_E + (size_t)(m0 + r) * NU + n4);
            a.x += cf * e.x; a.y += cf * e.y; a.z += cf * e.z; a.w += cf * e.w;
        }
        *(float4*)(g_wpart + (size_t)blockIdx.x * NU + n4) = a;
    }
}

// ---------------- k_final: parallel rank-select top-k ----------------
// rank(n) = #{j : w[j]>w[n] || (w[j]==w[n] && j<n)}; selected iff rank<k.
// Exactly reproduces jax top_k (lowest-index tie-break) + sorted index output.
__global__ __launch_bounds__(512) void k_final(float* __restrict__ out) {
    __shared__ float sw[NU];
    __shared__ unsigned bq[16];   // qk selection ballots (512 n / 32)
    __shared__ unsigned bv[8];    // v  selection ballots (256 n / 32)
    int b = blockIdx.x, t = threadIdx.x;
    int w = t >> 5, lane = t & 31;

    // reduce 32 chunk partials
    for (int n = t; n < NU; n += 512) {
        float a = 0.f;
#pragma unroll
        for (int c = 0; c < 32; c++) a += g_wpart[(size_t)(b * 32 + c) * NU + n];
        sw[n] = a;
    }
    __syncthreads();

    // ---- rank computations (broadcast shared sweeps) ----
    bool selq;
    {
        float v = sw[t]; int r = 0;
#pragma unroll 8
        for (int j = 0; j < 512; j++) {
            float o = sw[j];
            r += (o > v) || (o == v && j < t);
        }
        selq = (r < 64);
    }
    bool selv = false, selr = false, selval = false;
    if (t < 256) {
        float v = sw[512 + t]; int r = 0;
#pragma unroll 8
        for (int j = 0; j < 256; j++) {
            float o = sw[512 + j];
            r += (o > v) || (o == v && j < t);
        }
        selv = (r < 32);
    }
    if (t < 128) {
        float v = sw[768 + t]; int r = 0;
#pragma unroll 8
        for (int j = 0; j < 128; j++) {
            float o = sw[768 + j];
            r += (o > v) || (o == v && j < t);
        }
        selr = (r < 16);
    }
    if (t < 64) {
        float v = sw[896 + t]; int r = 0;
#pragma unroll
        for (int j = 0; j < 64; j++) {
            float o = sw[896 + j];
            r += (o > v) || (o == v && j < t);
        }
        selval = (r < 3);
    }

    unsigned mq = __ballot_sync(0xffffffffu, selq);
    unsigned mv = __ballot_sync(0xffffffffu, selv);
    if (lane == 0) {
        bq[w] = mq;
        if (w < 8) bv[w] = mv;
    }
    __syncthreads();

    // ---- outputs ----
    if (selq) {
        int pos = 0;
        for (int i = 0; i < w; i++) pos += __popc(bq[i]);
        pos += __popc(mq & ((1u << lane) - 1u));
        out[b * 64 + pos] = (float)t;                       // idx_qk (sorted)
    }
    if (selv) {
        int pos = 0;
        for (int i = 0; i < w; i++) pos += __popc(bv[i]);
        pos += __popc(mv & ((1u << lane) - 1u));
        out[512 + b * 32 + pos] = (float)t;                 // idx_v (sorted)
    }
    if (t < 128) {
        float val = selr ? sw[768 + t] : 0.f;
        out[768  + b * 128 + t] = val;                      // rel_Q
        out[1792 + b * 128 + t] = val;                      // rel_K
    }
    if (t < 64) {
        out[2816 + b * 64 + t] = selval ? sw[896 + t] : 0.f;  // val_w
    }
}

// ---------------- launch ----------------
extern "C" void kernel_launch(void* const* d_in, const int* in_sizes, int n_in,
                              void* d_out, int out_size) {
    const float* x    = (const float*)d_in[0];
    const float* imp  = (const float*)d_in[1];
    const float* W    = (const float*)d_in[2];
    const float* bias = (const float*)d_in[3];
    const float* emb  = (const float*)d_in[4];
    float* out = (float*)d_out;

    static bool attr_set = false;
    if (!attr_set) {
        cudaFuncSetAttribute(k_mega, cudaFuncAttributeMaxDynamicSharedMemorySize,
                             SMEM_FLOATS * 4);
        attr_set = true;
    }

    k_mega<<<MTOT / 128, 256, SMEM_FLOATS * 4>>>(x, W, bias, imp, emb);
    k_final<<<B_, 512>>>(out);
}

// round 11
// speedup vs baseline: 1.7040x; 1.1430x over previous
#include <cuda_runtime.h>
#include <cfloat>
#include <cstdint>

// Problem constants
#define B_    8
#define S_    4096
#define D_    1024
#define DS_   64
#define MTOT  32768      // B_*S_
#define NU    960        // used neurons: 512+256+128+64 (N_KNOW unused)

// Scratch (device globals — allocation-free per harness rules)
__device__ float g_E[(size_t)MTOT * NU];           // exp(logits) [32768][960]
__device__ float g_wpart[256 * NU];                // per-block partial w [256][960]

// ---------------- f32x2 packed-FMA helpers (phase 1) ----------------
__device__ __forceinline__ unsigned long long pk2s(float a) {
    unsigned long long r;
    asm("mov.b64 %0, {%1, %1};" : "=l"(r) : "f"(a));
    return r;
}
__device__ __forceinline__ void fma2(unsigned long long& acc,
                                     unsigned long long a, unsigned long long b) {
    asm("fma.rn.f32x2 %0, %1, %2, %0;" : "+l"(acc) : "l"(a), "l"(b));
}
__device__ __forceinline__ float2 upk2(unsigned long long v) {
    float2 f;
    asm("mov.b64 {%0, %1}, %2;" : "=f"(f.x), "=f"(f.y) : "l"(v));
    return f;
}

// ---------------- bf16 triple-split helpers ----------------
// cvt.rn.bf16x2.f32 d, a, b : a -> high half, b -> low half (CUTLASS convention)
__device__ __forceinline__ uint32_t cvt2bf(float lo, float hi) {
    uint32_t r;
    asm("cvt.rn.bf16x2.f32 %0, %2, %1;" : "=r"(r) : "f"(lo), "f"(hi));
    return r;
}
__device__ __forceinline__ float2 bf2f(uint32_t p) {
    return make_float2(__uint_as_float(p << 16), __uint_as_float(p & 0xffff0000u));
}
__device__ __forceinline__ void split3(float a, float b,
                                       uint32_t& u0, uint32_t& u1, uint32_t& u2) {
    u0 = cvt2bf(a, b);
    float2 f0 = bf2f(u0);
    float ra = a - f0.x, rb = b - f0.y;
    u1 = cvt2bf(ra, rb);
    float2 f1 = bf2f(u1);
    u2 = cvt2bf(ra - f1.x, rb - f1.y);
}

// ---------------- warp-level bf16 HMMA (baseline PTX, sm_80+) ----------------
__device__ __forceinline__ void mma_bf16(float* c, const uint32_t* a, const uint32_t* b) {
    asm volatile(
        "mma.sync.aligned.m16n8k16.row.col.f32.bf16.bf16.f32 "
        "{%0,%1,%2,%3}, {%4,%5,%6,%7}, {%8,%9}, {%0,%1,%2,%3};"
        : "+f"(c[0]), "+f"(c[1]), "+f"(c[2]), "+f"(c[3])
        : "r"(a[0]), "r"(a[1]), "r"(a[2]), "r"(a[3]), "r"(b[0]), "r"(b[1]));
}

// ================= smem layout =================
// floats:
//   snorm [960]        @ f0
//   sZ    [128][4]     @ f960
//   scoef [128][4]     @ f1472
//   shared region      @ f1984 (byte 7936), 55296 bytes:
//     phase1 aliases: sAx[32][132] @ f1984, sW[32][68] @ f6208
//     hs (bf16): 3 splits x [128 rows][72 k] @ bytes 7936 + s*18432
//     B slabs (bf16): 2 bufs x 3 splits x [64 n][72 k]
//       @ bytes 7936 + bq*27648 + s*9216   (aliases hs; A-frags in regs first)
#define SN_F      0
#define SZ_F      960
#define SC_F      1472
#define SAX_F     1984
#define SW_F      6208
#define HS_B      7936
#define HS_SPLIT  18432     // 128*144
#define BB_B      7936
#define BB_BUF    27648     // 3*9216
#define BB_SPLIT  9216      // 64*144
#define ROWB      144       // 72 bf16 per row (64 + 8 pad): conflict-free (36 words)
#define SMEM_BYTES 63232

__global__ __launch_bounds__(256, 2) void k_mega(const float* __restrict__ x,
                                                 const float* __restrict__ W,
                                                 const float* __restrict__ bias,
                                                 const float* __restrict__ imp,
                                                 const float* __restrict__ emb) {
    extern __shared__ __align__(16) float sm[];
    char*  smc   = (char*)sm;
    float* snorm = sm + SN_F;
    float* sZ    = sm + SZ_F;
    float* scoef = sm + SC_F;
    float* sAx   = sm + SAX_F;
    float* sW    = sm + SW_F;

    int tid  = threadIdx.x;
    int wid  = tid >> 5;
    int lane = tid & 31;
    int txn  = tid & 15;            // phase-1: 16 k-groups of 4
    int tym  = tid >> 4;            // phase-1: 16 m-groups of 8
    int m0   = blockIdx.x * 128;

    // ---- embedding inverse norms ----
    for (int n = tid; n < NU; n += 256) {
        const float4* er = (const float4*)(emb + (size_t)n * DS_);
        float ss = 0.f;
#pragma unroll
        for (int j = 0; j < 16; j++) {
            float4 v = er[j];
            ss += v.x * v.x + v.y * v.y + v.z * v.z + v.w * v.w;
        }
        snorm[n] = rsqrtf(ss);
    }

    // ---------- Phase 1: h = x @ W^T + bias (fp32 scalar, double-buffered) ----------
    {
        unsigned long long acc1[8][2];
#pragma unroll
        for (int i = 0; i < 8; i++) { acc1[i][0] = 0ull; acc1[i][1] = 0ull; }

        float4 xv[4], wv[2];
#pragma unroll
        for (int it = 0; it < 4; ++it) {
            int i = it * 256 + tid; int m = i >> 3; int c = i & 7;
            xv[it] = *(const float4*)(x + (size_t)(m0 + m) * D_ + c * 4);
        }
#pragma unroll
        for (int it = 0; it < 2; ++it) {
            int i = it * 256 + tid; int n = i >> 3; int c = i & 7;
            wv[it] = *(const float4*)(W + (size_t)n * D_ + c * 4);
        }

        for (int kb = 0; kb < D_; kb += 32) {
#pragma unroll
            for (int it = 0; it < 4; ++it) {
                int i = it * 256 + tid; int m = i >> 3; int c = i & 7;
                sAx[(c * 4 + 0) * 132 + m] = xv[it].x; sAx[(c * 4 + 1) * 132 + m] = xv[it].y;
                sAx[(c * 4 + 2) * 132 + m] = xv[it].z; sAx[(c * 4 + 3) * 132 + m] = xv[it].w;
            }
#pragma unroll
            for (int it = 0; it < 2; ++it) {
                int i = it * 256 + tid; int n = i >> 3; int c = i & 7;
                sW[(c * 4 + 0) * 68 + n] = wv[it].x; sW[(c * 4 + 1) * 68 + n] = wv[it].y;
                sW[(c * 4 + 2) * 68 + n] = wv[it].z; sW[(c * 4 + 3) * 68 + n] = wv[it].w;
            }
            __syncthreads();
            if (kb + 32 < D_) {
#pragma unroll
                for (int it = 0; it < 4; ++it) {
                    int i = it * 256 + tid; int m = i >> 3; int c = i & 7;
                    xv[it] = *(const float4*)(x + (size_t)(m0 + m) * D_ + kb + 32 + c * 4);
                }
#pragma unroll
                for (int it = 0; it < 2; ++it) {
                    int i = it * 256 + tid; int n = i >> 3; int c = i & 7;
                    wv[it] = *(const float4*)(W + (size_t)n * D_ + kb + 32 + c * 4);
                }
            }
#pragma unroll 8
            for (int kk = 0; kk < 32; ++kk) {
                float4 a0 = *(const float4*)&sAx[kk * 132 + tym * 8];
                float4 a1 = *(const float4*)&sAx[kk * 132 + tym * 8 + 4];
                ulonglong2 b = *(const ulonglong2*)&sW[kk * 68 + txn * 4];
                float av[8] = { a0.x, a0.y, a0.z, a0.w, a1.x, a1.y, a1.z, a1.w };
#pragma unroll
                for (int i = 0; i < 8; i++) {
                    unsigned long long ad = pk2s(av[i]);
                    fma2(acc1[i][0], ad, b.x);
                    fma2(acc1[i][1], ad, b.y);
                }
            }
            __syncthreads();
        }
        // epilogue: + bias, triple-split h rows into hs[s][m][k] bf16
        float b0 = bias[txn * 4 + 0], b1 = bias[txn * 4 + 1];
        float b2 = bias[txn * 4 + 2], b3 = bias[txn * 4 + 3];
#pragma unroll
        for (int i = 0; i < 8; i++) {
            int mrow = tym * 8 + i;
            float2 f0 = upk2(acc1[i][0]);
            float2 f1 = upk2(acc1[i][1]);
            float ha = f0.x + b0, hb = f0.y + b1, hc = f1.x + b2, hd = f1.y + b3;
            uint32_t p0, p1, p2, q0, q1, q2;
            split3(ha, hb, p0, p1, p2);
            split3(hc, hd, q0, q1, q2);
            uint32_t off = (uint32_t)(mrow * ROWB + txn * 8);
            *(uint2*)(smc + HS_B + 0 * HS_SPLIT + off) = make_uint2(p0, q0);
            *(uint2*)(smc + HS_B + 1 * HS_SPLIT + off) = make_uint2(p1, q1);
            *(uint2*)(smc + HS_B + 2 * HS_SPLIT + off) = make_uint2(p2, q2);
        }
        __syncthreads();
    }

    // ---------- load A fragments (resident in registers; hs region freed after) ----
    // m16n8k16 A frag: a0=[g][2t..+1], a1=[g+8][..], a2=[g][2t+8..], a3=[g+8][2t+8..]
    uint32_t Af[3][4][4];
    {
        int row0 = wid * 16 + (lane >> 2);
        int kofs = (lane & 3) * 2;
#pragma unroll
        for (int s = 0; s < 3; s++) {
            const char* base = smc + HS_B + s * HS_SPLIT;
#pragma unroll
            for (int ks = 0; ks < 4; ks++) {
                Af[s][ks][0] = *(const uint32_t*)(base + row0 * ROWB       + (ks * 16 + kofs) * 2);
                Af[s][ks][1] = *(const uint32_t*)(base + (row0 + 8) * ROWB + (ks * 16 + kofs) * 2);
                Af[s][ks][2] = *(const uint32_t*)(base + row0 * ROWB       + (ks * 16 + 8 + kofs) * 2);
                Af[s][ks][3] = *(const uint32_t*)(base + (row0 + 8) * ROWB + (ks * 16 + 8 + kofs) * 2);
            }
        }
    }
    __syncthreads();   // all warps done reading hs; B buffers may overwrite

    // ---------- Phase 2: 15 n-slabs of 64, bf16x6 emulated HMMA ----------
    // B slab loader: [64 n][64 k] triple-split bf16 into buf bq
    auto load_B = [&](int t, int bq) {
        int n0 = t * 64;
        char* dst = smc + BB_B + bq * BB_BUF;
#pragma unroll
        for (int it = 0; it < 4; ++it) {
            int i = it * 256 + tid; int n = i >> 2; int c = i & 3;   // c: float4 index (16 k each... 4 k)
            float s = snorm[n0 + n];
            float4 v = *(const float4*)(emb + (size_t)(n0 + n) * DS_ + c * 4 * 4);
            // NOTE: c covers k = 16c .. 16c+3?  -> need 4 float4 per n: c in 0..3 covers k=4c*4?  fix below
            (void)s; (void)v;
        }
        // corrected loader: 256 threads, 64 n x 4 float4-chunks (16 elems per thread)
#pragma unroll
        for (int it = 0; it < 4; ++it) {
            int i = it * 256 + tid; int n = i >> 4; int c = i & 15;  // c: float4 of k (4 k)
            float s = snorm[n0 + n];
            float4 v = *(const float4*)(emb + (size_t)(n0 + n) * DS_ + c * 4);
            float ea = v.x * s, eb = v.y * s, ec = v.z * s, ed = v.w * s;
            uint32_t p0, p1, p2, q0, q1, q2;
            split3(ea, eb, p0, p1, p2);
            split3(ec, ed, q0, q1, q2);
            uint32_t off = (uint32_t)(n * ROWB + c * 8);
            *(uint2*)(dst + 0 * BB_SPLIT + off) = make_uint2(p0, q0);
            *(uint2*)(dst + 1 * BB_SPLIT + off) = make_uint2(p1, q1);
            *(uint2*)(dst + 2 * BB_SPLIT + off) = make_uint2(p2, q2);
        }
    };

    float zacc[2][4] = {{0.f, 0.f, 0.f, 0.f}, {0.f, 0.f, 0.f, 0.f}};
    int row0 = wid * 16 + (lane >> 2);
    int kofs = (lane & 3) * 2;
    const int pa[6] = {0, 0, 1, 0, 1, 2};
    const int pb[6] = {0, 1, 0, 2, 1, 0};

    load_B(0, 0);
    __syncthreads();

    for (int t = 0; t < 15; ++t) {
        if (t + 1 < 15) load_B(t + 1, (t + 1) & 1);
        const char* bb = smc + BB_B + (t & 1) * BB_BUF;
        int g = (t < 8) ? 0 : (t < 12) ? 1 : (t < 14) ? 2 : 3;

        for (int nt = 0; nt < 8; ++nt) {
            // B fragments: b0=[2t..+1 k][g n], b1=[+8 k]
            uint32_t Bf[3][4][2];
            int nrow = nt * 8 + (lane >> 2);
#pragma unroll
            for (int s = 0; s < 3; s++) {
                const char* base = bb + s * BB_SPLIT;
#pragma unroll
                for (int ks = 0; ks < 4; ks++) {
                    Bf[s][ks][0] = *(const uint32_t*)(base + nrow * ROWB + (ks * 16 + kofs) * 2);
                    Bf[s][ks][1] = *(const uint32_t*)(base + nrow * ROWB + (ks * 16 + 8 + kofs) * 2);
                }
            }
            // 6 independent accumulator chains (ILP for tensor pipe)
            float C[6][4];
#pragma unroll
            for (int p = 0; p < 6; p++)
#pragma unroll
                for (int j = 0; j < 4; j++) C[p][j] = 0.f;
#pragma unroll
            for (int ks = 0; ks < 4; ks++)
#pragma unroll
                for (int p = 0; p < 6; p++)
                    mma_bf16(C[p], Af[pa[p]][ks], Bf[pb[p]][ks]);

            float c0 = ((C[0][0] + C[1][0]) + (C[2][0] + C[3][0])) + (C[4][0] + C[5][0]);
            float c1 = ((C[0][1] + C[1][1]) + (C[2][1] + C[3][1])) + (C[4][1] + C[5][1]);
            float c2 = ((C[0][2] + C[1][2]) + (C[2][2] + C[3][2])) + (C[4][2] + C[5][2]);
            float c3 = ((C[0][3] + C[1][3]) + (C[2][3] + C[3][3])) + (C[4][3] + C[5][3]);

            float e0 = __expf(c0), e1 = __expf(c1);
            float e2 = __expf(c2), e3 = __expf(c3);
            int col = t * 64 + nt * 8 + (lane & 3) * 2;
            *(float2*)(g_E + (size_t)(m0 + row0) * NU + col)     = make_float2(e0, e1);
            *(float2*)(g_E + (size_t)(m0 + row0 + 8) * NU + col) = make_float2(e2, e3);
            zacc[0][g] += e0 + e1;
            zacc[1][g] += e2 + e3;
        }
        __syncthreads();   // buf t consumed; buf t+1 committed
    }

    // ---------- row Z: quad-reduce (lanes sharing a row), write sZ ----------
#pragma unroll
    for (int h = 0; h < 2; h++)
#pragma unroll
        for (int g = 0; g < 4; g++) {
            float z = zacc[h][g];
            z += __shfl_xor_sync(0xffffffffu, z, 1);
            z += __shfl_xor_sync(0xffffffffu, z, 2);
            zacc[h][g] = z;
        }
    if ((lane & 3) == 0) {
#pragma unroll
        for (int g = 0; g < 4; g++) {
            sZ[row0 * 4 + g]       = zacc[0][g];
            sZ[(row0 + 8) * 4 + g] = zacc[1][g];
        }
    }
    __syncthreads();

    // ---------- coef = imp / Z ----------
    if (tid < 128) {
        float im = imp[m0 + tid];
#pragma unroll
        for (int g = 0; g < 4; g++) scoef[tid * 4 + g] = im * __frcp_rn(sZ[tid * 4 + g]);
    }
    __syncthreads();   // scoef ready; g_E writes visible block-wide

    // ---------- Phase 4: accum -> wpart[bx][960] ----------
    if (tid < 240) {
        int n4 = tid * 4;
        int g = (n4 < 512) ? 0 : (n4 < 768) ? 1 : (n4 < 896) ? 2 : 3;
        float4 a = make_float4(0.f, 0.f, 0.f, 0.f);
#pragma unroll 4
        for (int r = 0; r < 128; r++) {
            float cf = scoef[r * 4 + g];
            float4 e = *(const float4*)(g_E + (size_t)(m0 + r) * NU + n4);
            a.x += cf * e.x; a.y += cf * e.y; a.z += cf * e.z; a.w += cf * e.w;
        }
        *(float4*)(g_wpart + (size_t)blockIdx.x * NU + n4) = a;
    }
}

// ---------------- k_final: parallel rank-select top-k ----------------
__global__ __launch_bounds__(512) void k_final(float* __restrict__ out) {
    __shared__ float sw[NU];
    __shared__ unsigned bq[16];
    __shared__ unsigned bv[8];
    int b = blockIdx.x, t = threadIdx.x;
    int w = t >> 5, lane = t & 31;

    for (int n = t; n < NU; n += 512) {
        float a = 0.f;
#pragma unroll
        for (int c = 0; c < 32; c++) a += g_wpart[(size_t)(b * 32 + c) * NU + n];
        sw[n] = a;
    }
    __syncthreads();

    bool selq;
    {
        float v = sw[t]; int r = 0;
#pragma unroll 8
        for (int j = 0; j < 512; j++) {
            float o = sw[j];
            r += (o > v) || (o == v && j < t);
        }
        selq = (r < 64);
    }
    bool selv = false, selr = false, selval = false;
    if (t < 256) {
        float v = sw[512 + t]; int r = 0;
#pragma unroll 8
        for (int j = 0; j < 256; j++) {
            float o = sw[512 + j];
            r += (o > v) || (o == v && j < t);
        }
        selv = (r < 32);
    }
    if (t < 128) {
        float v = sw[768 + t]; int r = 0;
#pragma unroll 8
        for (int j = 0; j < 128; j++) {
            float o = sw[768 + j];
            r += (o > v) || (o == v && j < t);
        }
        selr = (r < 16);
    }
    if (t < 64) {
        float v = sw[896 + t]; int r = 0;
#pragma unroll
        for (int j = 0; j < 64; j++) {
            float o = sw[896 + j];
            r += (o > v) || (o == v && j < t);
        }
        selval = (r < 3);
    }

    unsigned mq = __ballot_sync(0xffffffffu, selq);
    unsigned mv = __ballot_sync(0xffffffffu, selv);
    if (lane == 0) {
        bq[w] = mq;
        if (w < 8) bv[w] = mv;
    }
    __syncthreads();

    if (selq) {
        int pos = 0;
        for (int i = 0; i < w; i++) pos += __popc(bq[i]);
        pos += __popc(mq & ((1u << lane) - 1u));
        out[b * 64 + pos] = (float)t;
    }
    if (selv) {
        int pos = 0;
        for (int i = 0; i < w; i++) pos += __popc(bv[i]);
        pos += __popc(mv & ((1u << lane) - 1u));
        out[512 + b * 32 + pos] = (float)t;
    }
    if (t < 128) {
        float val = selr ? sw[768 + t] : 0.f;
        out[768  + b * 128 + t] = val;
        out[1792 + b * 128 + t] = val;
    }
    if (t < 64) {
        out[2816 + b * 64 + t] = selval ? sw[896 + t] : 0.f;
    }
}

// ---------------- launch ----------------
extern "C" void kernel_launch(void* const* d_in, const int* in_sizes, int n_in,
                              void* d_out, int out_size) {
    const float* x    = (const float*)d_in[0];
    const float* imp  = (const float*)d_in[1];
    const float* W    = (const float*)d_in[2];
    const float* bias = (const float*)d_in[3];
    const float* emb  = (const float*)d_in[4];
    float* out = (float*)d_out;

    static bool attr_set = false;
    if (!attr_set) {
        cudaFuncSetAttribute(k_mega, cudaFuncAttributeMaxDynamicSharedMemorySize,
                             SMEM_BYTES);
        attr_set = true;
    }

    k_mega<<<MTOT / 128, 256, SMEM_BYTES>>>(x, W, bias, imp, emb);
    k_final<<<B_, 512>>>(out);
}

// round 12
// speedup vs baseline: 1.7120x; 1.0047x over previous
#include <cuda_runtime.h>
#include <cfloat>
#include <cstdint>

// Problem constants
#define B_    8
#define S_    4096
#define D_    1024
#define DS_   64
#define MTOT  32768      // B_*S_
#define NU    960        // used neurons: 512+256+128+64 (N_KNOW unused)

// Scratch (device globals — allocation-free per harness rules)
__device__ float g_E[(size_t)MTOT * NU];           // exp(logits) [32768][960]
__device__ float g_wpart[256 * NU];                // per-block partial w [256][960]

// ---------------- bf16 triple-split helpers ----------------
// cvt.rn.bf16x2.f32 d, a, b : a -> high half, b -> low half
__device__ __forceinline__ uint32_t cvt2bf(float lo, float hi) {
    uint32_t r;
    asm("cvt.rn.bf16x2.f32 %0, %2, %1;" : "=r"(r) : "f"(lo), "f"(hi));
    return r;
}
__device__ __forceinline__ float2 bf2f(uint32_t p) {
    return make_float2(__uint_as_float(p << 16), __uint_as_float(p & 0xffff0000u));
}
__device__ __forceinline__ void split3(float a, float b,
                                       uint32_t& u0, uint32_t& u1, uint32_t& u2) {
    u0 = cvt2bf(a, b);
    float2 f0 = bf2f(u0);
    float ra = a - f0.x, rb = b - f0.y;
    u1 = cvt2bf(ra, rb);
    float2 f1 = bf2f(u1);
    u2 = cvt2bf(ra - f1.x, rb - f1.y);
}

// ---------------- warp-level bf16 HMMA (baseline PTX, sm_80+) ----------------
__device__ __forceinline__ void mma_bf16(float* c, const uint32_t* a, const uint32_t* b) {
    asm volatile(
        "mma.sync.aligned.m16n8k16.row.col.f32.bf16.bf16.f32 "
        "{%0,%1,%2,%3}, {%4,%5,%6,%7}, {%8,%9}, {%0,%1,%2,%3};"
        : "+f"(c[0]), "+f"(c[1]), "+f"(c[2]), "+f"(c[3])
        : "r"(a[0]), "r"(a[1]), "r"(a[2]), "r"(a[3]), "r"(b[0]), "r"(b[1]));
}

// ---------------- fast exp on the FMA pipe (MUFU stays idle) ----------------
// exp(x) = 2^(x*log2e); deg-6 Taylor of 2^f on |f|<=0.5, rel err ~1e-7.
__device__ __forceinline__ float fexp(float x) {
    float y  = x * 1.4426950408889634f;
    float fi = rintf(y);
    float f  = y - fi;
    float p  = 1.54035304e-4f;
    p = __fmaf_rn(p, f, 1.33335581e-3f);
    p = __fmaf_rn(p, f, 9.61812911e-3f);
    p = __fmaf_rn(p, f, 5.55041087e-2f);
    p = __fmaf_rn(p, f, 2.40226507e-1f);
    p = __fmaf_rn(p, f, 6.93147181e-1f);
    p = __fmaf_rn(p, f, 1.0f);
    int i = (int)fi;
    return p * __int_as_float((i + 127) << 23);
}

// ================= smem layout (bytes) =================
//   snorm [960]f  @ 0      (3840)
//   sZ [128][4]f  @ 3840   (2048)
//   scoef[128][4]f@ 5888   (2048)
//   R2 @ 7936  (27648): phase-1 W splits  [3][64][144]B
//   R1 @ 35584 (55296): phase-1 x splits  [3][128][144]B
//                       phase-2 B ping-pong [2][3][64][144]B (aliased)
#define SN_B   0
#define SZ_B   3840
#define SC_B   5888
#define R2_B   7936
#define R1_B   35584
#define ROWB   144        // 72 bf16 per row (64 + 8 pad) — conflict-free
#define SMEM_BYTES 90880

__global__ __launch_bounds__(256, 2) void k_mega(const float* __restrict__ x,
                                                 const float* __restrict__ W,
                                                 const float* __restrict__ bias,
                                                 const float* __restrict__ imp,
                                                 const float* __restrict__ emb) {
    extern __shared__ __align__(16) char smc[];
    float* snorm = (float*)(smc + SN_B);
    float* sZ    = (float*)(smc + SZ_B);
    float* scoef = (float*)(smc + SC_B);

    int tid  = threadIdx.x;
    int wid  = tid >> 5;
    int lane = tid & 31;
    int m0   = blockIdx.x * 128;
    int row0 = wid * 16 + (lane >> 2);
    int kofs = (lane & 3) * 2;

    const int pa[6] = {0, 0, 1, 0, 1, 2};
    const int pb[6] = {0, 1, 0, 2, 1, 0};

    // ---- embedding inverse norms ----
    for (int n = tid; n < NU; n += 256) {
        const float4* er = (const float4*)(emb + (size_t)n * DS_);
        float ss = 0.f;
#pragma unroll
        for (int j = 0; j < 16; j++) {
            float4 v = er[j];
            ss += v.x * v.x + v.y * v.y + v.z * v.z + v.w * v.w;
        }
        snorm[n] = rsqrtf(ss);
    }

    // ---------- Phase 1: h = x @ W^T via bf16x6 HMMA over 16 k-chunks ----------
    float C[8][4];
#pragma unroll
    for (int nt = 0; nt < 8; nt++)
#pragma unroll
        for (int j = 0; j < 4; j++) C[nt][j] = 0.f;

    for (int ch = 0; ch < 16; ++ch) {
        int k0 = ch * 64;
        // x chunk [128 m][64 k] triple-split -> R1
#pragma unroll
        for (int it = 0; it < 8; ++it) {
            int i = it * 256 + tid; int r = i >> 4; int c = i & 15;
            float4 v = *(const float4*)(x + (size_t)(m0 + r) * D_ + k0 + c * 4);
            uint32_t p0, p1, p2, q0, q1, q2;
            split3(v.x, v.y, p0, p1, p2);
            split3(v.z, v.w, q0, q1, q2);
            uint32_t off = (uint32_t)(r * ROWB + c * 8);
            *(uint2*)(smc + R1_B + 0 * 18432 + off) = make_uint2(p0, q0);
            *(uint2*)(smc + R1_B + 1 * 18432 + off) = make_uint2(p1, q1);
            *(uint2*)(smc + R1_B + 2 * 18432 + off) = make_uint2(p2, q2);
        }
        // W chunk [64 n][64 k] triple-split -> R2
#pragma unroll
        for (int it = 0; it < 4; ++it) {
            int i = it * 256 + tid; int r = i >> 4; int c = i & 15;
            float4 v = *(const float4*)(W + (size_t)r * D_ + k0 + c * 4);
            uint32_t p0, p1, p2, q0, q1, q2;
            split3(v.x, v.y, p0, p1, p2);
            split3(v.z, v.w, q0, q1, q2);
            uint32_t off = (uint32_t)(r * ROWB + c * 8);
            *(uint2*)(smc + R2_B + 0 * 9216 + off) = make_uint2(p0, q0);
            *(uint2*)(smc + R2_B + 1 * 9216 + off) = make_uint2(p1, q1);
            *(uint2*)(smc + R2_B + 2 * 9216 + off) = make_uint2(p2, q2);
        }
        __syncthreads();

#pragma unroll
        for (int ks = 0; ks < 4; ++ks) {
            uint32_t Afc[3][4];
#pragma unroll
            for (int s = 0; s < 3; s++) {
                const char* base = smc + R1_B + s * 18432;
                Afc[s][0] = *(const uint32_t*)(base + row0 * ROWB       + (ks * 16 + kofs) * 2);
                Afc[s][1] = *(const uint32_t*)(base + (row0 + 8) * ROWB + (ks * 16 + kofs) * 2);
                Afc[s][2] = *(const uint32_t*)(base + row0 * ROWB       + (ks * 16 + 8 + kofs) * 2);
                Afc[s][3] = *(const uint32_t*)(base + (row0 + 8) * ROWB + (ks * 16 + 8 + kofs) * 2);
            }
#pragma unroll
            for (int nt = 0; nt < 8; ++nt) {
                uint32_t Bf[3][2];
                int nr = nt * 8 + (lane >> 2);
#pragma unroll
                for (int s = 0; s < 3; s++) {
                    const char* base = smc + R2_B + s * 9216;
                    Bf[s][0] = *(const uint32_t*)(base + nr * ROWB + (ks * 16 + kofs) * 2);
                    Bf[s][1] = *(const uint32_t*)(base + nr * ROWB + (ks * 16 + 8 + kofs) * 2);
                }
#pragma unroll
                for (int p = 0; p < 6; ++p)
                    mma_bf16(C[nt], Afc[pa[p]], Bf[pb[p]]);
            }
        }
        __syncthreads();
    }

    // ---------- bias + in-register convert: C frags -> phase-2 A frags ----------
    // C[nt]: c0,c1 = h[row0][nt*8+kofs,+1]; c2,c3 = h[row0+8][same cols]
    // Phase-2 A frag [ks]: a0=h[row0][ks*16+kofs], a1=h[row0+8][..], a2/a3 = +8 cols
    uint32_t Af[3][4][4];
#pragma unroll
    for (int ks = 0; ks < 4; ++ks) {
        int nt0 = 2 * ks, nt1 = 2 * ks + 1;
        float b00 = bias[nt0 * 8 + kofs], b01 = bias[nt0 * 8 + kofs + 1];
        float b10 = bias[nt1 * 8 + kofs], b11 = bias[nt1 * 8 + kofs + 1];
        split3(C[nt0][0] + b00, C[nt0][1] + b01, Af[0][ks][0], Af[1][ks][0], Af[2][ks][0]);
        split3(C[nt0][2] + b00, C[nt0][3] + b01, Af[0][ks][1], Af[1][ks][1], Af[2][ks][1]);
        split3(C[nt1][0] + b10, C[nt1][1] + b11, Af[0][ks][2], Af[1][ks][2], Af[2][ks][2]);
        split3(C[nt1][2] + b10, C[nt1][3] + b11, Af[0][ks][3], Af[1][ks][3], Af[2][ks][3]);
    }
    // (no sync needed: last chunk sync already separated smem reads from the
    //  phase-2 B-buffer writes below; epilogue was register-only)

    // ---------- Phase 2: 15 n-slabs of 64, bf16x6 HMMA ----------
    auto load_B = [&](int t, int bq) {
        int n0 = t * 64;
        char* dst = smc + R1_B + bq * 27648;
#pragma unroll
        for (int it = 0; it < 4; ++it) {
            int i = it * 256 + tid; int n = i >> 4; int c = i & 15;
            float s = snorm[n0 + n];
            float4 v = *(const float4*)(emb + (size_t)(n0 + n) * DS_ + c * 4);
            uint32_t p0, p1, p2, q0, q1, q2;
            split3(v.x * s, v.y * s, p0, p1, p2);
            split3(v.z * s, v.w * s, q0, q1, q2);
            uint32_t off = (uint32_t)(n * ROWB + c * 8);
            *(uint2*)(dst + 0 * 9216 + off) = make_uint2(p0, q0);
            *(uint2*)(dst + 1 * 9216 + off) = make_uint2(p1, q1);
            *(uint2*)(dst + 2 * 9216 + off) = make_uint2(p2, q2);
        }
    };

    float zacc[2][4] = {{0.f, 0.f, 0.f, 0.f}, {0.f, 0.f, 0.f, 0.f}};

    load_B(0, 0);
    __syncthreads();

    for (int t = 0; t < 15; ++t) {
        if (t + 1 < 15) load_B(t + 1, (t + 1) & 1);
        const char* bb = smc + R1_B + (t & 1) * 27648;
        int g = (t < 8) ? 0 : (t < 12) ? 1 : (t < 14) ? 2 : 3;

        for (int nt = 0; nt < 8; ++nt) {
            uint32_t Bf[3][4][2];
            int nr = nt * 8 + (lane >> 2);
#pragma unroll
            for (int s = 0; s < 3; s++) {
                const char* base = bb + s * 9216;
#pragma unroll
                for (int ks = 0; ks < 4; ks++) {
                    Bf[s][ks][0] = *(const uint32_t*)(base + nr * ROWB + (ks * 16 + kofs) * 2);
                    Bf[s][ks][1] = *(const uint32_t*)(base + nr * ROWB + (ks * 16 + 8 + kofs) * 2);
                }
            }
            float Cp[6][4];
#pragma unroll
            for (int p = 0; p < 6; p++)
#pragma unroll
                for (int j = 0; j < 4; j++) Cp[p][j] = 0.f;
#pragma unroll
            for (int ks = 0; ks < 4; ks++)
#pragma unroll
                for (int p = 0; p < 6; p++)
                    mma_bf16(Cp[p], Af[pa[p]][ks], Bf[pb[p]][ks]);

            float c0 = ((Cp[0][0] + Cp[1][0]) + (Cp[2][0] + Cp[3][0])) + (Cp[4][0] + Cp[5][0]);
            float c1 = ((Cp[0][1] + Cp[1][1]) + (Cp[2][1] + Cp[3][1])) + (Cp[4][1] + Cp[5][1]);
            float c2 = ((Cp[0][2] + Cp[1][2]) + (Cp[2][2] + Cp[3][2])) + (Cp[4][2] + Cp[5][2]);
            float c3 = ((Cp[0][3] + Cp[1][3]) + (Cp[2][3] + Cp[3][3])) + (Cp[4][3] + Cp[5][3]);

            float e0 = fexp(c0), e1 = fexp(c1);
            float e2 = fexp(c2), e3 = fexp(c3);
            int col = t * 64 + nt * 8 + kofs;
            *(float2*)(g_E + (size_t)(m0 + row0) * NU + col)     = make_float2(e0, e1);
            *(float2*)(g_E + (size_t)(m0 + row0 + 8) * NU + col) = make_float2(e2, e3);
            zacc[0][g] += e0 + e1;
            zacc[1][g] += e2 + e3;
        }
        __syncthreads();   // buf t consumed; buf t+1 committed
    }

    // ---------- row Z: quad-reduce, write sZ ----------
#pragma unroll
    for (int h = 0; h < 2; h++)
#pragma unroll
        for (int g = 0; g < 4; g++) {
            float z = zacc[h][g];
            z += __shfl_xor_sync(0xffffffffu, z, 1);
            z += __shfl_xor_sync(0xffffffffu, z, 2);
            zacc[h][g] = z;
        }
    if ((lane & 3) == 0) {
#pragma unroll
        for (int g = 0; g < 4; g++) {
            sZ[row0 * 4 + g]       = zacc[0][g];
            sZ[(row0 + 8) * 4 + g] = zacc[1][g];
        }
    }
    __syncthreads();

    // ---------- coef = imp / Z ----------
    if (tid < 128) {
        float im = imp[m0 + tid];
#pragma unroll
        for (int g = 0; g < 4; g++) scoef[tid * 4 + g] = im * __frcp_rn(sZ[tid * 4 + g]);
    }
    __syncthreads();   // scoef ready; g_E writes visible block-wide

    // ---------- Phase 4: accum -> wpart[bx][960] ----------
    if (tid < 240) {
        int n4 = tid * 4;
        int g = (n4 < 512) ? 0 : (n4 < 768) ? 1 : (n4 < 896) ? 2 : 3;
        float4 a = make_float4(0.f, 0.f, 0.f, 0.f);
#pragma unroll 4
        for (int r = 0; r < 128; r++) {
            float cf = scoef[r * 4 + g];
            float4 e = *(const float4*)(g_E + (size_t)(m0 + r) * NU + n4);
            a.x += cf * e.x; a.y += cf * e.y; a.z += cf * e.z; a.w += cf * e.w;
        }
        *(float4*)(g_wpart + (size_t)blockIdx.x * NU + n4) = a;
    }
}

// ---------------- k_final: parallel rank-select top-k (vectorized sweeps) ------
__global__ __launch_bounds__(512) void k_final(float* __restrict__ out) {
    __shared__ __align__(16) float sw[NU];
    __shared__ unsigned bq[16];
    __shared__ unsigned bv[8];
    int b = blockIdx.x, t = threadIdx.x;
    int w = t >> 5, lane = t & 31;

    for (int n = t; n < NU; n += 512) {
        float a = 0.f;
#pragma unroll
        for (int c = 0; c < 32; c++) a += g_wpart[(size_t)(b * 32 + c) * NU + n];
        sw[n] = a;
    }
    __syncthreads();

    const float4* s4 = (const float4*)sw;
    bool selq;
    {
        float v = sw[t]; int r = 0;
#pragma unroll 4
        for (int j4 = 0; j4 < 128; j4++) {
            float4 o = s4[j4]; int j = j4 * 4;
            r += (o.x > v) || (o.x == v && j < t);
            r += (o.y > v) || (o.y == v && j + 1 < t);
            r += (o.z > v) || (o.z == v && j + 2 < t);
            r += (o.w > v) || (o.w == v && j + 3 < t);
        }
        selq = (r < 64);
    }
    bool selv = false, selr = false, selval = false;
    if (t < 256) {
        float v = sw[512 + t]; int r = 0;
#pragma unroll 4
        for (int j4 = 0; j4 < 64; j4++) {
            float4 o = s4[128 + j4]; int j = j4 * 4;
            r += (o.x > v) || (o.x == v && j < t);
            r += (o.y > v) || (o.y == v && j + 1 < t);
            r += (o.z > v) || (o.z == v && j + 2 < t);
            r += (o.w > v) || (o.w == v && j + 3 < t);
        }
        selv = (r < 32);
    }
    if (t < 128) {
        float v = sw[768 + t]; int r = 0;
#pragma unroll 4
        for (int j4 = 0; j4 < 32; j4++) {
            float4 o = s4[192 + j4]; int j = j4 * 4;
            r += (o.x > v) || (o.x == v && j < t);
            r += (o.y > v) || (o.y == v && j + 1 < t);
            r += (o.z > v) || (o.z == v && j + 2 < t);
            r += (o.w > v) || (o.w == v && j + 3 < t);
        }
        selr = (r < 16);
    }
    if (t < 64) {
        float v = sw[896 + t]; int r = 0;
#pragma unroll
        for (int j4 = 0; j4 < 16; j4++) {
            float4 o = s4[224 + j4]; int j = j4 * 4;
            r += (o.x > v) || (o.x == v && j < t);
            r += (o.y > v) || (o.y == v && j + 1 < t);
            r += (o.z > v) || (o.z == v && j + 2 < t);
            r += (o.w > v) || (o.w == v && j + 3 < t);
        }
        selval = (r < 3);
    }

    unsigned mq = __ballot_sync(0xffffffffu, selq);
    unsigned mv = __ballot_sync(0xffffffffu, selv);
    if (lane == 0) {
        bq[w] = mq;
        if (w < 8) bv[w] = mv;
    }
    __syncthreads();

    if (selq) {
        int pos = 0;
        for (int i = 0; i < w; i++) pos += __popc(bq[i]);
        pos += __popc(mq & ((1u << lane) - 1u));
        out[b * 64 + pos] = (float)t;
    }
    if (selv) {
        int pos = 0;
        for (int i = 0; i < w; i++) pos += __popc(bv[i]);
        pos += __popc(mv & ((1u << lane) - 1u));
        out[512 + b * 32 + pos] = (float)t;
    }
    if (t < 128) {
        float val = selr ? sw[768 + t] : 0.f;
        out[768  + b * 128 + t] = val;
        out[1792 + b * 128 + t] = val;
    }
    if (t < 64) {
        out[2816 + b * 64 + t] = selval ? sw[896 + t] : 0.f;
    }
}

// ---------------- launch ----------------
extern "C" void kernel_launch(void* const* d_in, const int* in_sizes, int n_in,
                              void* d_out, int out_size) {
    const float* x    = (const float*)d_in[0];
    const float* imp  = (const float*)d_in[1];
    const float* W    = (const float*)d_in[2];
    const float* bias = (const float*)d_in[3];
    const float* emb  = (const float*)d_in[4];
    float* out = (float*)d_out;

    static bool attr_set = false;
    if (!attr_set) {
        cudaFuncSetAttribute(k_mega, cudaFuncAttributeMaxDynamicSharedMemorySize,
                             SMEM_BYTES);
        attr_set = true;
    }

    k_mega<<<MTOT / 128, 256, SMEM_BYTES>>>(x, W, bias, imp, emb);
    k_final<<<B_, 512>>>(out);
}